// round 2
// baseline (speedup 1.0000x reference)
#include <cuda_runtime.h>
#include <math.h>

#define S_LEN 2048
#define NH 16
#define HD 64
#define DM 1024
#define BB 2
#define M_TOK (BB * S_LEN)   // 4096

// -------- scratch (static device globals; allocation-free) --------
__device__ float g_qkv[(size_t)M_TOK * 3 * DM];  // 48 MB
__device__ float g_q[(size_t)M_TOK * DM];        // [B,H,S,Dh]
__device__ float g_k[(size_t)M_TOK * DM];
__device__ float g_v[(size_t)M_TOK * DM];
__device__ float g_ao[(size_t)M_TOK * DM];       // attn out, [B,S,H*Dh]
__device__ int   g_len[BB];

// ============================================================
// Mask length extraction — dtype-agnostic.
// attention_mask is prefix-true per batch; count true entries.
// Probe dtype: float32 (1.0f), int32 (bytes 01 00 ...), else 1-byte bool.
// ============================================================
__global__ void compute_lens(const void* __restrict__ mask)
{
    __shared__ int cnt;
    const int b = blockIdx.x;
    if (threadIdx.x == 0) cnt = 0;
    __syncthreads();

    const unsigned char* bytes = (const unsigned char*)mask;
    int dtype;  // 0 = u8/bool, 1 = int32, 2 = float32
    if (*(const float*)mask == 1.0f) dtype = 2;
    else if (bytes[0] == 1 && bytes[1] == 0) dtype = 1;
    else dtype = 0;

    int local = 0;
    for (int s = threadIdx.x; s < S_LEN; s += blockDim.x) {
        int v;
        if (dtype == 2)      v = (((const float*)mask)[b * S_LEN + s] != 0.0f);
        else if (dtype == 1) v = (((const int*)mask)[b * S_LEN + s] != 0);
        else                 v = (bytes[b * S_LEN + s] != 0);
        local += v;
    }
    atomicAdd(&cnt, local);
    __syncthreads();
    if (threadIdx.x == 0) g_len[b] = cnt;
}

// ============================================================
// Tiled fp32 SGEMM: C[m,n] = sum_k A[m,k] * B[n,k]
// A: [M,K] row-major, B: [N,K] row-major. M,N % 128 == 0, K % 16 == 0.
// 128x128 tile, BK=16, 256 threads, 8x8 per thread.
// ============================================================
__global__ __launch_bounds__(256) void sgemm_nt(
    const float* __restrict__ A, const float* __restrict__ B,
    float* __restrict__ C, int M, int N, int K)
{
    __shared__ float As[16][132];
    __shared__ float Bs[16][132];
    const int bm = blockIdx.y * 128;
    const int bn = blockIdx.x * 128;
    const int tid = threadIdx.x;
    const int ty = tid >> 4, tx = tid & 15;
    const int lr = tid >> 2;          // 0..63
    const int lk = (tid & 3) << 2;    // 0,4,8,12

    float acc[8][8];
#pragma unroll
    for (int i = 0; i < 8; i++)
#pragma unroll
        for (int j = 0; j < 8; j++) acc[i][j] = 0.f;

    for (int k0 = 0; k0 < K; k0 += 16) {
#pragma unroll
        for (int h = 0; h < 2; h++) {
            int row = lr + h * 64;
            float4 a = *(const float4*)&A[(size_t)(bm + row) * K + k0 + lk];
            As[lk + 0][row] = a.x; As[lk + 1][row] = a.y;
            As[lk + 2][row] = a.z; As[lk + 3][row] = a.w;
            float4 b = *(const float4*)&B[(size_t)(bn + row) * K + k0 + lk];
            Bs[lk + 0][row] = b.x; Bs[lk + 1][row] = b.y;
            Bs[lk + 2][row] = b.z; Bs[lk + 3][row] = b.w;
        }
        __syncthreads();
#pragma unroll
        for (int kk = 0; kk < 16; kk++) {
            float a[8], b[8];
            *(float4*)&a[0] = *(float4*)&As[kk][ty * 8];
            *(float4*)&a[4] = *(float4*)&As[kk][ty * 8 + 4];
            *(float4*)&b[0] = *(float4*)&Bs[kk][tx * 8];
            *(float4*)&b[4] = *(float4*)&Bs[kk][tx * 8 + 4];
#pragma unroll
            for (int i = 0; i < 8; i++)
#pragma unroll
                for (int j = 0; j < 8; j++)
                    acc[i][j] += a[i] * b[j];
        }
        __syncthreads();
    }
#pragma unroll
    for (int i = 0; i < 8; i++) {
        int row = bm + ty * 8 + i;
        float* cp = &C[(size_t)row * N + bn + tx * 8];
        *(float4*)cp       = make_float4(acc[i][0], acc[i][1], acc[i][2], acc[i][3]);
        *(float4*)(cp + 4) = make_float4(acc[i][4], acc[i][5], acc[i][6], acc[i][7]);
    }
}

// ============================================================
// RoPE (3-axis, interleaved pairs) + scatter to [B,H,S,Dh]
// segments: d in [0,20) axis x dim 20; [20,40) axis y dim 20; [40,64) axis z dim 24
// ============================================================
__global__ void rope_scatter(const float* __restrict__ qkv,
                             const int* __restrict__ pos_xyz,
                             float* __restrict__ Q, float* __restrict__ Kb,
                             float* __restrict__ V)
{
    int idx = blockIdx.x * blockDim.x + threadIdx.x;
    if (idx >= BB * S_LEN * NH * HD) return;
    int d = idx & 63;
    int h = (idx >> 6) & 15;
    int s = (idx >> 10) & (S_LEN - 1);
    int b = idx >> 21;
    int m = b * S_LEN + s;
    const float* base = qkv + (size_t)m * (3 * DM) + h * HD;

    int axis, dim, dd;
    if (d < 20)      { axis = 0; dim = 20; dd = d; }
    else if (d < 40) { axis = 1; dim = 20; dd = d - 20; }
    else             { axis = 2; dim = 24; dd = d - 40; }
    int pair = dd >> 1;
    float pos = (float)pos_xyz[m * 3 + axis];
    float inv = expf(-logf(10000.0f) * (float)(2 * pair) / (float)dim);
    float ang = pos * inv;
    float sn, cs;
    sincosf(ang, &sn, &cs);

    float xq  = base[d];
    float xqo = (dd & 1) ? base[d - 1] : base[d + 1];
    float xk  = base[DM + d];
    float xko = (dd & 1) ? base[DM + d - 1] : base[DM + d + 1];
    float vv  = base[2 * DM + d];

    float qr = (dd & 1) ? (xq * cs + xqo * sn) : (xq * cs - xqo * sn);
    float kr = (dd & 1) ? (xk * cs + xko * sn) : (xk * cs - xko * sn);

    size_t o = ((size_t)(b * NH + h) * S_LEN + s) * HD + d;
    Q[o] = qr; Kb[o] = kr; V[o] = vv;
}

// ============================================================
// Flash attention, fp32, 64x64 tiles, causal + key-length mask.
// Grid: (qtiles=32, b*h=32), 256 threads as 16x16, 4x4 per thread.
// Smem (dynamic): Qt[64][68] d-major, Kt[64][68] d-major,
//                 Ps[64][68] k-major, Vs[64][68] k-major.
// ============================================================
#define ATT_STRIDE 68
#define ATT_SMEM_BYTES (4 * 64 * ATT_STRIDE * 4)

__global__ __launch_bounds__(256) void flash_attn(
    const float* __restrict__ Q, const float* __restrict__ K,
    const float* __restrict__ V, const int* __restrict__ lens,
    float* __restrict__ Out)
{
    extern __shared__ float sm[];
    float* Qt = sm;
    float* Kt = Qt + 64 * ATT_STRIDE;
    float* Ps = Kt + 64 * ATT_STRIDE;
    float* Vs = Ps + 64 * ATT_STRIDE;

    const int qt = blockIdx.x;          // q tile
    const int bh = blockIdx.y;          // b*NH + h
    const int b  = bh >> 4;
    const float* Qg = Q + ((size_t)bh * S_LEN + qt * 64) * HD;
    const float* Kg = K + (size_t)bh * S_LEN * HD;
    const float* Vg = V + (size_t)bh * S_LEN * HD;
    const int klen = lens[b];
    const int h  = bh & 15;

    const int tid = threadIdx.x;
    const int ty = tid >> 4, tx = tid & 15;

    // load Q tile transposed: Qt[d][q]
    for (int idx = tid; idx < 64 * 16; idx += 256) {
        int q = idx >> 4, d0 = (idx & 15) << 2;
        float4 v = *(const float4*)&Qg[q * HD + d0];
        Qt[(d0 + 0) * ATT_STRIDE + q] = v.x;
        Qt[(d0 + 1) * ATT_STRIDE + q] = v.y;
        Qt[(d0 + 2) * ATT_STRIDE + q] = v.z;
        Qt[(d0 + 3) * ATT_STRIDE + q] = v.w;
    }

    float oacc[4][4];
    float mrow[4], lrow[4];
#pragma unroll
    for (int i = 0; i < 4; i++) {
        mrow[i] = -1e30f; lrow[i] = 0.f;
#pragma unroll
        for (int j = 0; j < 4; j++) oacc[i][j] = 0.f;
    }

    const int ntiles = qt + 1;   // causal: only tiles t <= qt
    for (int t = 0; t < ntiles; t++) {
        // load K tile transposed: Kt[d][k]; V tile k-major: Vs[k][d]
        for (int idx = tid; idx < 64 * 16; idx += 256) {
            int kk = idx >> 4, d0 = (idx & 15) << 2;
            float4 v = *(const float4*)&Kg[(t * 64 + kk) * HD + d0];
            Kt[(d0 + 0) * ATT_STRIDE + kk] = v.x;
            Kt[(d0 + 1) * ATT_STRIDE + kk] = v.y;
            Kt[(d0 + 2) * ATT_STRIDE + kk] = v.z;
            Kt[(d0 + 3) * ATT_STRIDE + kk] = v.w;
            *(float4*)&Vs[kk * ATT_STRIDE + d0] =
                *(const float4*)&Vg[(t * 64 + kk) * HD + d0];
        }
        __syncthreads();

        // S = Q K^T (contraction over d)
        float acc[4][4];
#pragma unroll
        for (int i = 0; i < 4; i++)
#pragma unroll
            for (int j = 0; j < 4; j++) acc[i][j] = 0.f;
#pragma unroll
        for (int d = 0; d < 64; d++) {
            float qv[4], kv[4];
            *(float4*)qv = *(float4*)&Qt[d * ATT_STRIDE + ty * 4];
            *(float4*)kv = *(float4*)&Kt[d * ATT_STRIDE + tx * 4];
#pragma unroll
            for (int i = 0; i < 4; i++)
#pragma unroll
                for (int j = 0; j < 4; j++)
                    acc[i][j] += qv[i] * kv[j];
        }

        // scale + causal + length mask
        const int qg0 = qt * 64 + ty * 4;
        const int kg0 = t * 64 + tx * 4;
#pragma unroll
        for (int i = 0; i < 4; i++)
#pragma unroll
            for (int j = 0; j < 4; j++) {
                int kg = kg0 + j;
                bool valid = (kg <= qg0 + i) && (kg < klen);
                acc[i][j] = valid ? acc[i][j] * 0.125f : -1e30f;
            }

        // online softmax (row reductions over 16 lanes of same ty)
#pragma unroll
        for (int i = 0; i < 4; i++) {
            float rm = fmaxf(fmaxf(acc[i][0], acc[i][1]),
                             fmaxf(acc[i][2], acc[i][3]));
#pragma unroll
            for (int off = 8; off > 0; off >>= 1)
                rm = fmaxf(rm, __shfl_xor_sync(0xffffffffu, rm, off));
            float mnew = fmaxf(mrow[i], rm);
            float alpha = __expf(mrow[i] - mnew);
            mrow[i] = mnew;
            float rl = 0.f;
#pragma unroll
            for (int j = 0; j < 4; j++) {
                float p = __expf(acc[i][j] - mnew);
                acc[i][j] = p;
                rl += p;
            }
#pragma unroll
            for (int off = 8; off > 0; off >>= 1)
                rl += __shfl_xor_sync(0xffffffffu, rl, off);
            lrow[i] = lrow[i] * alpha + rl;
#pragma unroll
            for (int j = 0; j < 4; j++) oacc[i][j] *= alpha;
        }

        // store P transposed: Ps[k][q]
#pragma unroll
        for (int i = 0; i < 4; i++)
#pragma unroll
            for (int j = 0; j < 4; j++)
                Ps[(tx * 4 + j) * ATT_STRIDE + ty * 4 + i] = acc[i][j];
        __syncthreads();

        // O += P V (contraction over k)
#pragma unroll
        for (int kk = 0; kk < 64; kk++) {
            float pv[4], vv[4];
            *(float4*)pv = *(float4*)&Ps[kk * ATT_STRIDE + ty * 4];
            *(float4*)vv = *(float4*)&Vs[kk * ATT_STRIDE + tx * 4];
#pragma unroll
            for (int i = 0; i < 4; i++)
#pragma unroll
                for (int j = 0; j < 4; j++)
                    oacc[i][j] += pv[i] * vv[j];
        }
        __syncthreads();   // protect Kt/Vs/Ps before next tile's loads
    }

    // epilogue -> [B,S,H*Dh]
#pragma unroll
    for (int i = 0; i < 4; i++) {
        int qg = qt * 64 + ty * 4 + i;
        float invl = 1.0f / lrow[i];
        float4 r = make_float4(oacc[i][0] * invl, oacc[i][1] * invl,
                               oacc[i][2] * invl, oacc[i][3] * invl);
        *(float4*)&Out[((size_t)(b * S_LEN + qg)) * DM + h * HD + tx * 4] = r;
    }
}

// ============================================================
extern "C" void kernel_launch(void* const* d_in, const int* in_sizes, int n_in,
                              void* d_out, int out_size)
{
    const float* hidden = (const float*)d_in[0];
    const float* w_qkv  = (const float*)d_in[1];
    const float* w_out  = (const float*)d_in[2];
    const void*  attn_mask = d_in[3];
    // d_in[4] = causal_mask (implicit in kernel)
    const int* pos_xyz = (const int*)d_in[5];
    float* out = (float*)d_out;

    float *qkv, *q, *k, *v, *ao;
    int* lens;
    cudaGetSymbolAddress((void**)&qkv,  g_qkv);
    cudaGetSymbolAddress((void**)&q,    g_q);
    cudaGetSymbolAddress((void**)&k,    g_k);
    cudaGetSymbolAddress((void**)&v,    g_v);
    cudaGetSymbolAddress((void**)&ao,   g_ao);
    cudaGetSymbolAddress((void**)&lens, g_len);

    // 0. Extract per-batch valid lengths from the (dtype-unknown) bool mask
    compute_lens<<<BB, 256>>>(attn_mask);

    // 1. QKV projection: [4096,1024] x [3072,1024]^T -> [4096,3072]
    {
        dim3 grid(3 * DM / 128, M_TOK / 128);
        sgemm_nt<<<grid, 256>>>(hidden, w_qkv, qkv, M_TOK, 3 * DM, DM);
    }

    // 2. RoPE + scatter to [B,H,S,Dh]
    {
        int total = BB * S_LEN * NH * HD;
        rope_scatter<<<(total + 255) / 256, 256>>>(qkv, pos_xyz, q, k, v);
    }

    // 3. Flash attention
    {
        cudaFuncSetAttribute(flash_attn,
                             cudaFuncAttributeMaxDynamicSharedMemorySize,
                             ATT_SMEM_BYTES);
        dim3 grid(S_LEN / 64, BB * NH);
        flash_attn<<<grid, 256, ATT_SMEM_BYTES>>>(q, k, v, lens, ao);
    }

    // 4. Output projection: [4096,1024] x [1024,1024]^T -> [4096,1024]
    {
        dim3 grid(DM / 128, M_TOK / 128);
        sgemm_nt<<<grid, 256>>>(ao, w_out, out, M_TOK, DM, DM);
    }
}

// round 3
// speedup vs baseline: 1.4466x; 1.4466x over previous
#include <cuda_runtime.h>
#include <math.h>
#include <stdint.h>

#define S_LEN 2048
#define NH 16
#define HD 64
#define DM 1024
#define BB 2
#define M_TOK (BB * S_LEN)   // 4096

// -------- scratch (static device globals; allocation-free) --------
__device__ float g_qkv[(size_t)M_TOK * 3 * DM];  // 48 MB
__device__ float g_q[(size_t)M_TOK * DM];        // [B,H,S,Dh]
__device__ float g_k[(size_t)M_TOK * DM];
__device__ float g_v[(size_t)M_TOK * DM];
__device__ float g_ao[(size_t)M_TOK * DM];       // attn out, [B,S,H*Dh]
__device__ int   g_len[BB];

// ============================================================
// Mask length extraction — dtype-agnostic (prefix-true mask).
// ============================================================
__global__ void compute_lens(const void* __restrict__ mask)
{
    __shared__ int cnt;
    const int b = blockIdx.x;
    if (threadIdx.x == 0) cnt = 0;
    __syncthreads();

    const unsigned char* bytes = (const unsigned char*)mask;
    int dtype;  // 0 = u8/bool, 1 = int32, 2 = float32
    if (*(const float*)mask == 1.0f) dtype = 2;
    else if (bytes[0] == 1 && bytes[1] == 0) dtype = 1;
    else dtype = 0;

    int local = 0;
    for (int s = threadIdx.x; s < S_LEN; s += blockDim.x) {
        int v;
        if (dtype == 2)      v = (((const float*)mask)[b * S_LEN + s] != 0.0f);
        else if (dtype == 1) v = (((const int*)mask)[b * S_LEN + s] != 0);
        else                 v = (bytes[b * S_LEN + s] != 0);
        local += v;
    }
    atomicAdd(&cnt, local);
    __syncthreads();
    if (threadIdx.x == 0) g_len[b] = cnt;
}

// ============================================================
// tf32 tensor-core GEMM: C[m,n] = sum_k A[m,k] * B[n,k]
// A: [M,K] row-major, B: [N,K] row-major (= col-major KxN -> mma "col").
// Block 128x128, BK=32, 256 thr = 8 warps (2 m x 4 n), warp tile 64x32.
// mma.sync.m16n8k8.tf32, fp32 accumulate. Smem stride 36 -> conflict-free
// fragment loads (bank == lane for both A and B patterns).
// ============================================================
#define GS 36   // smem row stride (floats)

__device__ __forceinline__ uint32_t f2tf32(float f) {
    uint32_t r;
    asm("cvt.rna.tf32.f32 %0, %1;" : "=r"(r) : "f"(f));
    return r;
}

__global__ __launch_bounds__(256) void gemm_tf32_nt(
    const float* __restrict__ A, const float* __restrict__ B,
    float* __restrict__ C, int M, int N, int K)
{
    __shared__ uint32_t As[128 * GS];
    __shared__ uint32_t Bs[128 * GS];

    const int bm = blockIdx.y * 128;
    const int bn = blockIdx.x * 128;
    const int tid = threadIdx.x;
    const int wid = tid >> 5;
    const int lane = tid & 31;
    const int wm = (wid & 1) * 64;   // warp m offset in tile
    const int wn = (wid >> 1) * 32;  // warp n offset in tile
    const int lr = lane >> 2;        // 0..7
    const int lc = lane & 3;         // 0..3

    // gmem->smem assignment: thread t loads row t>>1, k-offset (t&1)*16, 16 floats
    const int grow = tid >> 1;
    const int gk   = (tid & 1) * 16;

    float c[4][4][4];
#pragma unroll
    for (int i = 0; i < 4; i++)
#pragma unroll
        for (int j = 0; j < 4; j++)
#pragma unroll
            for (int r = 0; r < 4; r++) c[i][j][r] = 0.f;

    for (int k0 = 0; k0 < K; k0 += 32) {
        // load A tile [128 x 32] and B tile [128 x 32]
#pragma unroll
        for (int v = 0; v < 4; v++) {
            float4 a = *(const float4*)&A[(size_t)(bm + grow) * K + k0 + gk + v * 4];
            As[grow * GS + gk + v * 4 + 0] = f2tf32(a.x);
            As[grow * GS + gk + v * 4 + 1] = f2tf32(a.y);
            As[grow * GS + gk + v * 4 + 2] = f2tf32(a.z);
            As[grow * GS + gk + v * 4 + 3] = f2tf32(a.w);
            float4 b = *(const float4*)&B[(size_t)(bn + grow) * K + k0 + gk + v * 4];
            Bs[grow * GS + gk + v * 4 + 0] = f2tf32(b.x);
            Bs[grow * GS + gk + v * 4 + 1] = f2tf32(b.y);
            Bs[grow * GS + gk + v * 4 + 2] = f2tf32(b.z);
            Bs[grow * GS + gk + v * 4 + 3] = f2tf32(b.w);
        }
        __syncthreads();

#pragma unroll
        for (int ks = 0; ks < 4; ks++) {   // 4 x k8 steps
            const int kb = ks * 8;
            uint32_t af[4][4], bf[4][2];
#pragma unroll
            for (int mf = 0; mf < 4; mf++) {
                int r0 = wm + mf * 16 + lr;
                af[mf][0] = As[(r0    ) * GS + kb + lc    ];
                af[mf][1] = As[(r0 + 8) * GS + kb + lc    ];
                af[mf][2] = As[(r0    ) * GS + kb + lc + 4];
                af[mf][3] = As[(r0 + 8) * GS + kb + lc + 4];
            }
#pragma unroll
            for (int nf = 0; nf < 4; nf++) {
                int n0 = wn + nf * 8 + lr;
                bf[nf][0] = Bs[n0 * GS + kb + lc    ];
                bf[nf][1] = Bs[n0 * GS + kb + lc + 4];
            }
#pragma unroll
            for (int mf = 0; mf < 4; mf++)
#pragma unroll
                for (int nf = 0; nf < 4; nf++) {
                    asm volatile(
                        "mma.sync.aligned.m16n8k8.row.col.f32.tf32.tf32.f32 "
                        "{%0,%1,%2,%3}, {%4,%5,%6,%7}, {%8,%9}, {%0,%1,%2,%3};\n"
                        : "+f"(c[mf][nf][0]), "+f"(c[mf][nf][1]),
                          "+f"(c[mf][nf][2]), "+f"(c[mf][nf][3])
                        : "r"(af[mf][0]), "r"(af[mf][1]),
                          "r"(af[mf][2]), "r"(af[mf][3]),
                          "r"(bf[nf][0]), "r"(bf[nf][1]));
                }
        }
        __syncthreads();
    }

    // epilogue: c0,c1 at (row, 2*lc), (row, 2*lc+1); c2,c3 at row+8
#pragma unroll
    for (int mf = 0; mf < 4; mf++) {
#pragma unroll
        for (int nf = 0; nf < 4; nf++) {
            int row = bm + wm + mf * 16 + lr;
            int col = bn + wn + nf * 8 + lc * 2;
            *(float2*)&C[(size_t)row * N + col] =
                make_float2(c[mf][nf][0], c[mf][nf][1]);
            *(float2*)&C[(size_t)(row + 8) * N + col] =
                make_float2(c[mf][nf][2], c[mf][nf][3]);
        }
    }
}

// ============================================================
// RoPE (3-axis, interleaved pairs) + scatter to [B,H,S,Dh]
// ============================================================
__global__ void rope_scatter(const float* __restrict__ qkv,
                             const int* __restrict__ pos_xyz,
                             float* __restrict__ Q, float* __restrict__ Kb,
                             float* __restrict__ V)
{
    int idx = blockIdx.x * blockDim.x + threadIdx.x;
    if (idx >= BB * S_LEN * NH * HD) return;
    int d = idx & 63;
    int h = (idx >> 6) & 15;
    int s = (idx >> 10) & (S_LEN - 1);
    int b = idx >> 21;
    int m = b * S_LEN + s;
    const float* base = qkv + (size_t)m * (3 * DM) + h * HD;

    int axis, dim, dd;
    if (d < 20)      { axis = 0; dim = 20; dd = d; }
    else if (d < 40) { axis = 1; dim = 20; dd = d - 20; }
    else             { axis = 2; dim = 24; dd = d - 40; }
    int pair = dd >> 1;
    float pos = (float)pos_xyz[m * 3 + axis];
    float inv = expf(-logf(10000.0f) * (float)(2 * pair) / (float)dim);
    float ang = pos * inv;
    float sn, cs;
    sincosf(ang, &sn, &cs);

    float xq  = base[d];
    float xqo = (dd & 1) ? base[d - 1] : base[d + 1];
    float xk  = base[DM + d];
    float xko = (dd & 1) ? base[DM + d - 1] : base[DM + d + 1];
    float vv  = base[2 * DM + d];

    float qr = (dd & 1) ? (xq * cs + xqo * sn) : (xq * cs - xqo * sn);
    float kr = (dd & 1) ? (xk * cs + xko * sn) : (xk * cs - xko * sn);

    size_t o = ((size_t)(b * NH + h) * S_LEN + s) * HD + d;
    Q[o] = qr; Kb[o] = kr; V[o] = vv;
}

// ============================================================
// Flash attention, fp32, 64x64 tiles, causal + key-length mask.
// ============================================================
#define ATT_STRIDE 68
#define ATT_SMEM_BYTES (4 * 64 * ATT_STRIDE * 4)

__global__ __launch_bounds__(256) void flash_attn(
    const float* __restrict__ Q, const float* __restrict__ K,
    const float* __restrict__ V, const int* __restrict__ lens,
    float* __restrict__ Out)
{
    extern __shared__ float sm[];
    float* Qt = sm;
    float* Kt = Qt + 64 * ATT_STRIDE;
    float* Ps = Kt + 64 * ATT_STRIDE;
    float* Vs = Ps + 64 * ATT_STRIDE;

    const int qt = blockIdx.x;
    const int bh = blockIdx.y;
    const int b  = bh >> 4;
    const float* Qg = Q + ((size_t)bh * S_LEN + qt * 64) * HD;
    const float* Kg = K + (size_t)bh * S_LEN * HD;
    const float* Vg = V + (size_t)bh * S_LEN * HD;
    const int klen = lens[b];
    const int h  = bh & 15;

    const int tid = threadIdx.x;
    const int ty = tid >> 4, tx = tid & 15;

    for (int idx = tid; idx < 64 * 16; idx += 256) {
        int q = idx >> 4, d0 = (idx & 15) << 2;
        float4 v = *(const float4*)&Qg[q * HD + d0];
        Qt[(d0 + 0) * ATT_STRIDE + q] = v.x;
        Qt[(d0 + 1) * ATT_STRIDE + q] = v.y;
        Qt[(d0 + 2) * ATT_STRIDE + q] = v.z;
        Qt[(d0 + 3) * ATT_STRIDE + q] = v.w;
    }

    float oacc[4][4];
    float mrow[4], lrow[4];
#pragma unroll
    for (int i = 0; i < 4; i++) {
        mrow[i] = -1e30f; lrow[i] = 0.f;
#pragma unroll
        for (int j = 0; j < 4; j++) oacc[i][j] = 0.f;
    }

    const int ntiles = qt + 1;
    for (int t = 0; t < ntiles; t++) {
        for (int idx = tid; idx < 64 * 16; idx += 256) {
            int kk = idx >> 4, d0 = (idx & 15) << 2;
            float4 v = *(const float4*)&Kg[(t * 64 + kk) * HD + d0];
            Kt[(d0 + 0) * ATT_STRIDE + kk] = v.x;
            Kt[(d0 + 1) * ATT_STRIDE + kk] = v.y;
            Kt[(d0 + 2) * ATT_STRIDE + kk] = v.z;
            Kt[(d0 + 3) * ATT_STRIDE + kk] = v.w;
            *(float4*)&Vs[kk * ATT_STRIDE + d0] =
                *(const float4*)&Vg[(t * 64 + kk) * HD + d0];
        }
        __syncthreads();

        float acc[4][4];
#pragma unroll
        for (int i = 0; i < 4; i++)
#pragma unroll
            for (int j = 0; j < 4; j++) acc[i][j] = 0.f;
#pragma unroll
        for (int d = 0; d < 64; d++) {
            float qv[4], kv[4];
            *(float4*)qv = *(float4*)&Qt[d * ATT_STRIDE + ty * 4];
            *(float4*)kv = *(float4*)&Kt[d * ATT_STRIDE + tx * 4];
#pragma unroll
            for (int i = 0; i < 4; i++)
#pragma unroll
                for (int j = 0; j < 4; j++)
                    acc[i][j] += qv[i] * kv[j];
        }

        const int qg0 = qt * 64 + ty * 4;
        const int kg0 = t * 64 + tx * 4;
#pragma unroll
        for (int i = 0; i < 4; i++)
#pragma unroll
            for (int j = 0; j < 4; j++) {
                int kg = kg0 + j;
                bool valid = (kg <= qg0 + i) && (kg < klen);
                acc[i][j] = valid ? acc[i][j] * 0.125f : -1e30f;
            }

#pragma unroll
        for (int i = 0; i < 4; i++) {
            float rm = fmaxf(fmaxf(acc[i][0], acc[i][1]),
                             fmaxf(acc[i][2], acc[i][3]));
#pragma unroll
            for (int off = 8; off > 0; off >>= 1)
                rm = fmaxf(rm, __shfl_xor_sync(0xffffffffu, rm, off));
            float mnew = fmaxf(mrow[i], rm);
            float alpha = __expf(mrow[i] - mnew);
            mrow[i] = mnew;
            float rl = 0.f;
#pragma unroll
            for (int j = 0; j < 4; j++) {
                float p = __expf(acc[i][j] - mnew);
                acc[i][j] = p;
                rl += p;
            }
#pragma unroll
            for (int off = 8; off > 0; off >>= 1)
                rl += __shfl_xor_sync(0xffffffffu, rl, off);
            lrow[i] = lrow[i] * alpha + rl;
#pragma unroll
            for (int j = 0; j < 4; j++) oacc[i][j] *= alpha;
        }

#pragma unroll
        for (int i = 0; i < 4; i++)
#pragma unroll
            for (int j = 0; j < 4; j++)
                Ps[(tx * 4 + j) * ATT_STRIDE + ty * 4 + i] = acc[i][j];
        __syncthreads();

#pragma unroll
        for (int kk = 0; kk < 64; kk++) {
            float pv[4], vv[4];
            *(float4*)pv = *(float4*)&Ps[kk * ATT_STRIDE + ty * 4];
            *(float4*)vv = *(float4*)&Vs[kk * ATT_STRIDE + tx * 4];
#pragma unroll
            for (int i = 0; i < 4; i++)
#pragma unroll
                for (int j = 0; j < 4; j++)
                    oacc[i][j] += pv[i] * vv[j];
        }
        __syncthreads();
    }

#pragma unroll
    for (int i = 0; i < 4; i++) {
        int qg = qt * 64 + ty * 4 + i;
        float invl = 1.0f / lrow[i];
        float4 r = make_float4(oacc[i][0] * invl, oacc[i][1] * invl,
                               oacc[i][2] * invl, oacc[i][3] * invl);
        *(float4*)&Out[((size_t)(b * S_LEN + qg)) * DM + h * HD + tx * 4] = r;
    }
}

// ============================================================
extern "C" void kernel_launch(void* const* d_in, const int* in_sizes, int n_in,
                              void* d_out, int out_size)
{
    const float* hidden = (const float*)d_in[0];
    const float* w_qkv  = (const float*)d_in[1];
    const float* w_out  = (const float*)d_in[2];
    const void*  attn_mask = d_in[3];
    // d_in[4] = causal_mask (implicit)
    const int* pos_xyz = (const int*)d_in[5];
    float* out = (float*)d_out;

    float *qkv, *q, *k, *v, *ao;
    int* lens;
    cudaGetSymbolAddress((void**)&qkv,  g_qkv);
    cudaGetSymbolAddress((void**)&q,    g_q);
    cudaGetSymbolAddress((void**)&k,    g_k);
    cudaGetSymbolAddress((void**)&v,    g_v);
    cudaGetSymbolAddress((void**)&ao,   g_ao);
    cudaGetSymbolAddress((void**)&lens, g_len);

    compute_lens<<<BB, 256>>>(attn_mask);

    // 1. QKV projection (tf32 tensor cores)
    {
        dim3 grid(3 * DM / 128, M_TOK / 128);
        gemm_tf32_nt<<<grid, 256>>>(hidden, w_qkv, qkv, M_TOK, 3 * DM, DM);
    }

    // 2. RoPE + scatter
    {
        int total = BB * S_LEN * NH * HD;
        rope_scatter<<<(total + 255) / 256, 256>>>(qkv, pos_xyz, q, k, v);
    }

    // 3. Flash attention
    {
        cudaFuncSetAttribute(flash_attn,
                             cudaFuncAttributeMaxDynamicSharedMemorySize,
                             ATT_SMEM_BYTES);
        dim3 grid(S_LEN / 64, BB * NH);
        flash_attn<<<grid, 256, ATT_SMEM_BYTES>>>(q, k, v, lens, ao);
    }

    // 4. Output projection (tf32 tensor cores)
    {
        dim3 grid(DM / 128, M_TOK / 128);
        gemm_tf32_nt<<<grid, 256>>>(ao, w_out, out, M_TOK, DM, DM);
    }
}

// round 4
// speedup vs baseline: 2.0088x; 1.3886x over previous
#include <cuda_runtime.h>
#include <math.h>
#include <stdint.h>

#define S_LEN 2048
#define NH 16
#define HD 64
#define DM 1024
#define BB 2
#define M_TOK (BB * S_LEN)   // 4096

// -------- scratch (static device globals; allocation-free) --------
__device__ float g_qkv[(size_t)M_TOK * 3 * DM];
__device__ float g_q[(size_t)M_TOK * DM];        // [B,H,S,Dh]
__device__ float g_k[(size_t)M_TOK * DM];
__device__ float g_v[(size_t)M_TOK * DM];
__device__ float g_ao[(size_t)M_TOK * DM];       // attn out, [B,S,H*Dh]
__device__ int   g_len[BB];

__device__ __forceinline__ uint32_t f2tf32(float f) {
    uint32_t r;
    asm("cvt.rna.tf32.f32 %0, %1;" : "=r"(r) : "f"(f));
    return r;
}

#define MMA_TF32(c, a, b0, b1)                                              \
    asm volatile(                                                           \
        "mma.sync.aligned.m16n8k8.row.col.f32.tf32.tf32.f32 "               \
        "{%0,%1,%2,%3}, {%4,%5,%6,%7}, {%8,%9}, {%0,%1,%2,%3};"             \
        : "+f"((c)[0]), "+f"((c)[1]), "+f"((c)[2]), "+f"((c)[3])            \
        : "r"((a)[0]), "r"((a)[1]), "r"((a)[2]), "r"((a)[3]),               \
          "r"(b0), "r"(b1))

// ============================================================
// Mask length extraction — dtype-agnostic (prefix-true mask).
// ============================================================
__global__ void compute_lens(const void* __restrict__ mask)
{
    __shared__ int cnt;
    const int b = blockIdx.x;
    if (threadIdx.x == 0) cnt = 0;
    __syncthreads();

    const unsigned char* bytes = (const unsigned char*)mask;
    int dtype;  // 0 = u8/bool, 1 = int32, 2 = float32
    if (*(const float*)mask == 1.0f) dtype = 2;
    else if (bytes[0] == 1 && bytes[1] == 0) dtype = 1;
    else dtype = 0;

    int local = 0;
    for (int s = threadIdx.x; s < S_LEN; s += blockDim.x) {
        int v;
        if (dtype == 2)      v = (((const float*)mask)[b * S_LEN + s] != 0.0f);
        else if (dtype == 1) v = (((const int*)mask)[b * S_LEN + s] != 0);
        else                 v = (bytes[b * S_LEN + s] != 0);
        local += v;
    }
    atomicAdd(&cnt, local);
    __syncthreads();
    if (threadIdx.x == 0) g_len[b] = cnt;
}

// ============================================================
// tf32 tensor-core GEMM: C[m,n] = sum_k A[m,k] * B[n,k]
// (unchanged from R3 — passing at 5.5e-4)
// ============================================================
#define GS 36

__global__ __launch_bounds__(256) void gemm_tf32_nt(
    const float* __restrict__ A, const float* __restrict__ B,
    float* __restrict__ C, int M, int N, int K)
{
    __shared__ uint32_t As[128 * GS];
    __shared__ uint32_t Bs[128 * GS];

    const int bm = blockIdx.y * 128;
    const int bn = blockIdx.x * 128;
    const int tid = threadIdx.x;
    const int wid = tid >> 5;
    const int lane = tid & 31;
    const int wm = (wid & 1) * 64;
    const int wn = (wid >> 1) * 32;
    const int lr = lane >> 2;
    const int lc = lane & 3;
    const int grow = tid >> 1;
    const int gk   = (tid & 1) * 16;

    float c[4][4][4];
#pragma unroll
    for (int i = 0; i < 4; i++)
#pragma unroll
        for (int j = 0; j < 4; j++)
#pragma unroll
            for (int r = 0; r < 4; r++) c[i][j][r] = 0.f;

    for (int k0 = 0; k0 < K; k0 += 32) {
#pragma unroll
        for (int v = 0; v < 4; v++) {
            float4 a = *(const float4*)&A[(size_t)(bm + grow) * K + k0 + gk + v * 4];
            As[grow * GS + gk + v * 4 + 0] = f2tf32(a.x);
            As[grow * GS + gk + v * 4 + 1] = f2tf32(a.y);
            As[grow * GS + gk + v * 4 + 2] = f2tf32(a.z);
            As[grow * GS + gk + v * 4 + 3] = f2tf32(a.w);
            float4 b = *(const float4*)&B[(size_t)(bn + grow) * K + k0 + gk + v * 4];
            Bs[grow * GS + gk + v * 4 + 0] = f2tf32(b.x);
            Bs[grow * GS + gk + v * 4 + 1] = f2tf32(b.y);
            Bs[grow * GS + gk + v * 4 + 2] = f2tf32(b.z);
            Bs[grow * GS + gk + v * 4 + 3] = f2tf32(b.w);
        }
        __syncthreads();

#pragma unroll
        for (int ks = 0; ks < 4; ks++) {
            const int kb = ks * 8;
            uint32_t af[4][4], bf[4][2];
#pragma unroll
            for (int mf = 0; mf < 4; mf++) {
                int r0 = wm + mf * 16 + lr;
                af[mf][0] = As[(r0    ) * GS + kb + lc    ];
                af[mf][1] = As[(r0 + 8) * GS + kb + lc    ];
                af[mf][2] = As[(r0    ) * GS + kb + lc + 4];
                af[mf][3] = As[(r0 + 8) * GS + kb + lc + 4];
            }
#pragma unroll
            for (int nf = 0; nf < 4; nf++) {
                int n0 = wn + nf * 8 + lr;
                bf[nf][0] = Bs[n0 * GS + kb + lc    ];
                bf[nf][1] = Bs[n0 * GS + kb + lc + 4];
            }
#pragma unroll
            for (int mf = 0; mf < 4; mf++)
#pragma unroll
                for (int nf = 0; nf < 4; nf++)
                    MMA_TF32(c[mf][nf], af[mf], bf[nf][0], bf[nf][1]);
        }
        __syncthreads();
    }

#pragma unroll
    for (int mf = 0; mf < 4; mf++) {
#pragma unroll
        for (int nf = 0; nf < 4; nf++) {
            int row = bm + wm + mf * 16 + lr;
            int col = bn + wn + nf * 8 + lc * 2;
            *(float2*)&C[(size_t)row * N + col] =
                make_float2(c[mf][nf][0], c[mf][nf][1]);
            *(float2*)&C[(size_t)(row + 8) * N + col] =
                make_float2(c[mf][nf][2], c[mf][nf][3]);
        }
    }
}

// ============================================================
// RoPE (3-axis, interleaved pairs) + scatter to [B,H,S,Dh]
// ============================================================
__global__ void rope_scatter(const float* __restrict__ qkv,
                             const int* __restrict__ pos_xyz,
                             float* __restrict__ Q, float* __restrict__ Kb,
                             float* __restrict__ V)
{
    int idx = blockIdx.x * blockDim.x + threadIdx.x;
    if (idx >= BB * S_LEN * NH * HD) return;
    int d = idx & 63;
    int h = (idx >> 6) & 15;
    int s = (idx >> 10) & (S_LEN - 1);
    int b = idx >> 21;
    int m = b * S_LEN + s;
    const float* base = qkv + (size_t)m * (3 * DM) + h * HD;

    int axis, dim, dd;
    if (d < 20)      { axis = 0; dim = 20; dd = d; }
    else if (d < 40) { axis = 1; dim = 20; dd = d - 20; }
    else             { axis = 2; dim = 24; dd = d - 40; }
    int pair = dd >> 1;
    float pos = (float)pos_xyz[m * 3 + axis];
    float inv = expf(-logf(10000.0f) * (float)(2 * pair) / (float)dim);
    float ang = pos * inv;
    float sn, cs;
    sincosf(ang, &sn, &cs);

    float xq  = base[d];
    float xqo = (dd & 1) ? base[d - 1] : base[d + 1];
    float xk  = base[DM + d];
    float xko = (dd & 1) ? base[DM + d - 1] : base[DM + d + 1];
    float vv  = base[2 * DM + d];

    float qr = (dd & 1) ? (xq * cs + xqo * sn) : (xq * cs - xqo * sn);
    float kr = (dd & 1) ? (xk * cs + xko * sn) : (xk * cs - xko * sn);

    size_t o = ((size_t)(b * NH + h) * S_LEN + s) * HD + d;
    Q[o] = qr; Kb[o] = kr; V[o] = vv;
}

// ============================================================
// Flash attention, tf32 tensor cores. 64x64 tiles, 128 thr = 4 warps,
// each warp owns 16 q-rows. S-phase uses 3xtf32 split (near-fp32 scores);
// PV plain tf32. Q held in registers (hi/lo frags).
// Smem: Ksh[64][68], Ksl[64][68], Vt[64][68] (V transposed), Ps[4][16][76].
// ============================================================
#define FS_KS 68
#define FS_PS 76
#define FA_SMEM_WORDS (3 * 64 * FS_KS + 4 * 16 * FS_PS)
#define FA_SMEM_BYTES (FA_SMEM_WORDS * 4)

__global__ __launch_bounds__(128, 2) void flash_attn_tf32(
    const float* __restrict__ Q, const float* __restrict__ K,
    const float* __restrict__ V, const int* __restrict__ lens,
    float* __restrict__ Out)
{
    extern __shared__ uint32_t smu[];
    uint32_t* Ksh = smu;
    uint32_t* Ksl = smu + 64 * FS_KS;
    uint32_t* Vt  = smu + 2 * 64 * FS_KS;
    uint32_t* Ps  = smu + 3 * 64 * FS_KS;   // also Q staging

    const int qt = blockIdx.x;
    const int bh = blockIdx.y;
    const int b  = bh >> 4;
    const int h  = bh & 15;
    const float* Qg = Q + ((size_t)bh * S_LEN + qt * 64) * HD;
    const float* Kg = K + (size_t)bh * S_LEN * HD;
    const float* Vg = V + (size_t)bh * S_LEN * HD;
    const int klen = lens[b];

    const int tid = threadIdx.x;
    const int wq = tid >> 5;
    const int lane = tid & 31;
    const int lr = lane >> 2;
    const int lc = lane & 3;
    const int r0 = wq * 16 + lr;           // warp-local q row (and +8)

    // ---- stage Q (f32) then build persistent hi/lo fragments ----
    float* Qstage = (float*)Ps;
    for (int idx = tid; idx < 64 * 16; idx += 128) {
        int q = idx >> 4, d0 = (idx & 15) << 2;
        float4 v = *(const float4*)&Qg[q * HD + d0];
        Qstage[q * FS_KS + d0 + 0] = v.x;
        Qstage[q * FS_KS + d0 + 1] = v.y;
        Qstage[q * FS_KS + d0 + 2] = v.z;
        Qstage[q * FS_KS + d0 + 3] = v.w;
    }
    __syncthreads();

    uint32_t qh[8][4], ql[8][4];
#pragma unroll
    for (int kb = 0; kb < 8; kb++) {
        float f[4];
        f[0] = Qstage[(r0    ) * FS_KS + kb * 8 + lc    ];
        f[1] = Qstage[(r0 + 8) * FS_KS + kb * 8 + lc    ];
        f[2] = Qstage[(r0    ) * FS_KS + kb * 8 + lc + 4];
        f[3] = Qstage[(r0 + 8) * FS_KS + kb * 8 + lc + 4];
#pragma unroll
        for (int i = 0; i < 4; i++) {
            qh[kb][i] = f2tf32(f[i]);
            ql[kb][i] = f2tf32(f[i] - __uint_as_float(qh[kb][i]));
        }
    }
    __syncthreads();

    float oacc[8][4];
#pragma unroll
    for (int nf = 0; nf < 8; nf++)
#pragma unroll
        for (int i = 0; i < 4; i++) oacc[nf][i] = 0.f;
    float mrow0 = -1e30f, mrow1 = -1e30f;
    float lrow0 = 0.f, lrow1 = 0.f;

    const int qg0 = qt * 64 + r0;

    for (int t = 0; t <= qt; t++) {
        if (t * 64 >= klen) break;   // prefix mask: this & later tiles fully masked

        // ---- stage K (hi/lo) and V^T ----
        for (int idx = tid; idx < 64 * 16; idx += 128) {
            {
                int key = idx >> 4, d0 = (idx & 15) << 2;
                float4 kk = *(const float4*)&Kg[(t * 64 + key) * HD + d0];
                uint32_t h0 = f2tf32(kk.x), h1 = f2tf32(kk.y);
                uint32_t h2 = f2tf32(kk.z), h3 = f2tf32(kk.w);
                *(uint4*)&Ksh[key * FS_KS + d0] = make_uint4(h0, h1, h2, h3);
                *(uint4*)&Ksl[key * FS_KS + d0] = make_uint4(
                    f2tf32(kk.x - __uint_as_float(h0)),
                    f2tf32(kk.y - __uint_as_float(h1)),
                    f2tf32(kk.z - __uint_as_float(h2)),
                    f2tf32(kk.w - __uint_as_float(h3)));
            }
            {
                int key = idx & 63, dc = idx >> 6;
                float4 vv = *(const float4*)&Vg[(t * 64 + key) * HD + dc * 4];
                Vt[(dc * 4 + 0) * FS_KS + key] = f2tf32(vv.x);
                Vt[(dc * 4 + 1) * FS_KS + key] = f2tf32(vv.y);
                Vt[(dc * 4 + 2) * FS_KS + key] = f2tf32(vv.z);
                Vt[(dc * 4 + 3) * FS_KS + key] = f2tf32(vv.w);
            }
        }
        __syncthreads();

        // ---- S = Q K^T (3xtf32) ----
        float sf[8][4];
#pragma unroll
        for (int nf = 0; nf < 8; nf++)
#pragma unroll
            for (int i = 0; i < 4; i++) sf[nf][i] = 0.f;

#pragma unroll
        for (int kb = 0; kb < 8; kb++) {
#pragma unroll
            for (int nf = 0; nf < 8; nf++) {
                int n0 = nf * 8 + lr;
                uint32_t bh0 = Ksh[n0 * FS_KS + kb * 8 + lc];
                uint32_t bh1 = Ksh[n0 * FS_KS + kb * 8 + lc + 4];
                uint32_t bl0 = Ksl[n0 * FS_KS + kb * 8 + lc];
                uint32_t bl1 = Ksl[n0 * FS_KS + kb * 8 + lc + 4];
                MMA_TF32(sf[nf], qh[kb], bh0, bh1);
                MMA_TF32(sf[nf], ql[kb], bh0, bh1);
                MMA_TF32(sf[nf], qh[kb], bl0, bl1);
            }
        }

        // ---- mask + scale ----
        const bool edge = (t == qt) || ((t + 1) * 64 > klen);
#pragma unroll
        for (int nf = 0; nf < 8; nf++) {
            if (edge) {
                int kg = t * 64 + nf * 8 + lc * 2;
                sf[nf][0] = (kg     <= qg0     && kg     < klen) ? sf[nf][0] * 0.125f : -1e30f;
                sf[nf][1] = (kg + 1 <= qg0     && kg + 1 < klen) ? sf[nf][1] * 0.125f : -1e30f;
                sf[nf][2] = (kg     <= qg0 + 8 && kg     < klen) ? sf[nf][2] * 0.125f : -1e30f;
                sf[nf][3] = (kg + 1 <= qg0 + 8 && kg + 1 < klen) ? sf[nf][3] * 0.125f : -1e30f;
            } else {
                sf[nf][0] *= 0.125f; sf[nf][1] *= 0.125f;
                sf[nf][2] *= 0.125f; sf[nf][3] *= 0.125f;
            }
        }

        // ---- online softmax (rows r0 -> regs 0,1 ; r0+8 -> regs 2,3) ----
        float m0 = -1e30f, m1 = -1e30f;
#pragma unroll
        for (int nf = 0; nf < 8; nf++) {
            m0 = fmaxf(m0, fmaxf(sf[nf][0], sf[nf][1]));
            m1 = fmaxf(m1, fmaxf(sf[nf][2], sf[nf][3]));
        }
        m0 = fmaxf(m0, __shfl_xor_sync(0xffffffffu, m0, 1));
        m0 = fmaxf(m0, __shfl_xor_sync(0xffffffffu, m0, 2));
        m1 = fmaxf(m1, __shfl_xor_sync(0xffffffffu, m1, 1));
        m1 = fmaxf(m1, __shfl_xor_sync(0xffffffffu, m1, 2));

        float mn0 = fmaxf(mrow0, m0), mn1 = fmaxf(mrow1, m1);
        float al0 = __expf(mrow0 - mn0), al1 = __expf(mrow1 - mn1);
        mrow0 = mn0; mrow1 = mn1;

        float s0 = 0.f, s1 = 0.f;
#pragma unroll
        for (int nf = 0; nf < 8; nf++) {
            float p0 = __expf(sf[nf][0] - mn0);
            float p1 = __expf(sf[nf][1] - mn0);
            float p2 = __expf(sf[nf][2] - mn1);
            float p3 = __expf(sf[nf][3] - mn1);
            sf[nf][0] = p0; sf[nf][1] = p1; sf[nf][2] = p2; sf[nf][3] = p3;
            s0 += p0 + p1; s1 += p2 + p3;
        }
        s0 += __shfl_xor_sync(0xffffffffu, s0, 1);
        s0 += __shfl_xor_sync(0xffffffffu, s0, 2);
        s1 += __shfl_xor_sync(0xffffffffu, s1, 1);
        s1 += __shfl_xor_sync(0xffffffffu, s1, 2);
        lrow0 = lrow0 * al0 + s0;
        lrow1 = lrow1 * al1 + s1;

#pragma unroll
        for (int nf = 0; nf < 8; nf++) {
            oacc[nf][0] *= al0; oacc[nf][1] *= al0;
            oacc[nf][2] *= al1; oacc[nf][3] *= al1;
        }

        // ---- store P (tf32) to warp-private smem ----
        uint32_t* PsW = Ps + wq * 16 * FS_PS;
#pragma unroll
        for (int nf = 0; nf < 8; nf++) {
            int col = nf * 8 + lc * 2;
            PsW[ lr      * FS_PS + col    ] = f2tf32(sf[nf][0]);
            PsW[ lr      * FS_PS + col + 1] = f2tf32(sf[nf][1]);
            PsW[(lr + 8) * FS_PS + col    ] = f2tf32(sf[nf][2]);
            PsW[(lr + 8) * FS_PS + col + 1] = f2tf32(sf[nf][3]);
        }
        __syncwarp();

        // ---- O += P V ----
#pragma unroll
        for (int kb = 0; kb < 8; kb++) {
            uint32_t af[4];
            af[0] = PsW[ lr      * FS_PS + kb * 8 + lc    ];
            af[1] = PsW[(lr + 8) * FS_PS + kb * 8 + lc    ];
            af[2] = PsW[ lr      * FS_PS + kb * 8 + lc + 4];
            af[3] = PsW[(lr + 8) * FS_PS + kb * 8 + lc + 4];
#pragma unroll
            for (int nf = 0; nf < 8; nf++) {
                int n0 = nf * 8 + lr;
                uint32_t b0 = Vt[n0 * FS_KS + kb * 8 + lc];
                uint32_t b1 = Vt[n0 * FS_KS + kb * 8 + lc + 4];
                MMA_TF32(oacc[nf], af, b0, b1);
            }
        }
        __syncthreads();
    }

    // ---- epilogue -> [B,S,H*Dh] ----
    float inv0 = 1.0f / lrow0, inv1 = 1.0f / lrow1;
#pragma unroll
    for (int nf = 0; nf < 8; nf++) {
        int col = h * HD + nf * 8 + lc * 2;
        *(float2*)&Out[((size_t)(b * S_LEN + qg0    )) * DM + col] =
            make_float2(oacc[nf][0] * inv0, oacc[nf][1] * inv0);
        *(float2*)&Out[((size_t)(b * S_LEN + qg0 + 8)) * DM + col] =
            make_float2(oacc[nf][2] * inv1, oacc[nf][3] * inv1);
    }
}

// ============================================================
extern "C" void kernel_launch(void* const* d_in, const int* in_sizes, int n_in,
                              void* d_out, int out_size)
{
    const float* hidden = (const float*)d_in[0];
    const float* w_qkv  = (const float*)d_in[1];
    const float* w_out  = (const float*)d_in[2];
    const void*  attn_mask = d_in[3];
    // d_in[4] = causal_mask (implicit)
    const int* pos_xyz = (const int*)d_in[5];
    float* out = (float*)d_out;

    float *qkv, *q, *k, *v, *ao;
    int* lens;
    cudaGetSymbolAddress((void**)&qkv,  g_qkv);
    cudaGetSymbolAddress((void**)&q,    g_q);
    cudaGetSymbolAddress((void**)&k,    g_k);
    cudaGetSymbolAddress((void**)&v,    g_v);
    cudaGetSymbolAddress((void**)&ao,   g_ao);
    cudaGetSymbolAddress((void**)&lens, g_len);

    compute_lens<<<BB, 256>>>(attn_mask);

    // 1. QKV projection (tf32 tensor cores)
    {
        dim3 grid(3 * DM / 128, M_TOK / 128);
        gemm_tf32_nt<<<grid, 256>>>(hidden, w_qkv, qkv, M_TOK, 3 * DM, DM);
    }

    // 2. RoPE + scatter
    {
        int total = BB * S_LEN * NH * HD;
        rope_scatter<<<(total + 255) / 256, 256>>>(qkv, pos_xyz, q, k, v);
    }

    // 3. Flash attention (tf32 tensor cores, 3xtf32 scores)
    {
        cudaFuncSetAttribute(flash_attn_tf32,
                             cudaFuncAttributeMaxDynamicSharedMemorySize,
                             FA_SMEM_BYTES);
        dim3 grid(S_LEN / 64, BB * NH);
        flash_attn_tf32<<<grid, 128, FA_SMEM_BYTES>>>(q, k, v, lens, ao);
    }

    // 4. Output projection (tf32 tensor cores)
    {
        dim3 grid(DM / 128, M_TOK / 128);
        gemm_tf32_nt<<<grid, 256>>>(ao, w_out, out, M_TOK, DM, DM);
    }
}

// round 5
// speedup vs baseline: 2.2595x; 1.1248x over previous
#include <cuda_runtime.h>
#include <math.h>
#include <stdint.h>

#define S_LEN 2048
#define NH 16
#define HD 64
#define DM 1024
#define BB 2
#define M_TOK (BB * S_LEN)   // 4096

// -------- scratch (static device globals; allocation-free) --------
__device__ float g_qkv[(size_t)M_TOK * 3 * DM];
__device__ float g_q[(size_t)M_TOK * DM];        // [B,H,S,Dh]
__device__ float g_k[(size_t)M_TOK * DM];
__device__ float g_v[(size_t)M_TOK * DM];
__device__ float g_ao[(size_t)M_TOK * DM];       // attn out, [B,S,H*Dh]
__device__ int   g_len[BB];

__device__ __forceinline__ uint32_t f2tf32(float f) {
    uint32_t r;
    asm("cvt.rna.tf32.f32 %0, %1;" : "=r"(r) : "f"(f));
    return r;
}

#define MMA_TF32(c, a, b0, b1)                                              \
    asm volatile(                                                           \
        "mma.sync.aligned.m16n8k8.row.col.f32.tf32.tf32.f32 "               \
        "{%0,%1,%2,%3}, {%4,%5,%6,%7}, {%8,%9}, {%0,%1,%2,%3};"             \
        : "+f"((c)[0]), "+f"((c)[1]), "+f"((c)[2]), "+f"((c)[3])            \
        : "r"((a)[0]), "r"((a)[1]), "r"((a)[2]), "r"((a)[3]),               \
          "r"(b0), "r"(b1))

__device__ __forceinline__ void cpa16(void* smem, const void* gmem) {
    uint32_t s = (uint32_t)__cvta_generic_to_shared(smem);
    asm volatile("cp.async.cg.shared.global [%0], [%1], 16;" :: "r"(s), "l"(gmem));
}
#define CPA_COMMIT() asm volatile("cp.async.commit_group;")
#define CPA_WAIT1()  asm volatile("cp.async.wait_group 1;")

// ============================================================
// Mask length extraction — dtype-agnostic (prefix-true mask).
// ============================================================
__global__ void compute_lens(const void* __restrict__ mask)
{
    __shared__ int cnt;
    const int b = blockIdx.x;
    if (threadIdx.x == 0) cnt = 0;
    __syncthreads();

    const unsigned char* bytes = (const unsigned char*)mask;
    int dtype;  // 0 = u8/bool, 1 = int32, 2 = float32
    if (*(const float*)mask == 1.0f) dtype = 2;
    else if (bytes[0] == 1 && bytes[1] == 0) dtype = 1;
    else dtype = 0;

    int local = 0;
    for (int s = threadIdx.x; s < S_LEN; s += blockDim.x) {
        int v;
        if (dtype == 2)      v = (((const float*)mask)[b * S_LEN + s] != 0.0f);
        else if (dtype == 1) v = (((const int*)mask)[b * S_LEN + s] != 0);
        else                 v = (bytes[b * S_LEN + s] != 0);
        local += v;
    }
    atomicAdd(&cnt, local);
    __syncthreads();
    if (threadIdx.x == 0) g_len[b] = cnt;
}

// ============================================================
// tf32 GEMM, cp.async double-buffered. C[m,n] = sum_k A[m,k]*B[n,k].
// Raw f32 in smem; cvt.rna at fragment load. 128x128 tile, BK=32.
// ============================================================
#define GS 36

__global__ __launch_bounds__(256) void gemm_tf32_nt(
    const float* __restrict__ A, const float* __restrict__ B,
    float* __restrict__ C, int M, int N, int K)
{
    __shared__ float As[2][128 * GS];
    __shared__ float Bs[2][128 * GS];

    const int bm = blockIdx.y * 128;
    const int bn = blockIdx.x * 128;
    const int tid = threadIdx.x;
    const int wid = tid >> 5;
    const int lane = tid & 31;
    const int wm = (wid & 1) * 64;
    const int wn = (wid >> 1) * 32;
    const int lr = lane >> 2;
    const int lc = lane & 3;

    float c[4][4][4];
#pragma unroll
    for (int i = 0; i < 4; i++)
#pragma unroll
        for (int j = 0; j < 4; j++)
#pragma unroll
            for (int r = 0; r < 4; r++) c[i][j][r] = 0.f;

    auto issue = [&](int st, int k0) {
#pragma unroll
        for (int i = 0; i < 4; i++) {
            int cid = tid + i * 256;       // 0..1023
            int row = cid >> 3;
            int col = (cid & 7) * 4;
            cpa16(&As[st][row * GS + col], &A[(size_t)(bm + row) * K + k0 + col]);
            cpa16(&Bs[st][row * GS + col], &B[(size_t)(bn + row) * K + k0 + col]);
        }
        CPA_COMMIT();
    };

    const int nIt = K / 32;
    issue(0, 0);

    for (int it = 0; it < nIt; it++) {
        const int st = it & 1;
        if (it + 1 < nIt) issue(st ^ 1, (it + 1) * 32);
        else CPA_COMMIT();
        CPA_WAIT1();
        __syncthreads();

#pragma unroll
        for (int ks = 0; ks < 4; ks++) {
            const int kb = ks * 8;
            uint32_t af[4][4], bf[4][2];
#pragma unroll
            for (int mf = 0; mf < 4; mf++) {
                int r0 = wm + mf * 16 + lr;
                af[mf][0] = f2tf32(As[st][(r0    ) * GS + kb + lc    ]);
                af[mf][1] = f2tf32(As[st][(r0 + 8) * GS + kb + lc    ]);
                af[mf][2] = f2tf32(As[st][(r0    ) * GS + kb + lc + 4]);
                af[mf][3] = f2tf32(As[st][(r0 + 8) * GS + kb + lc + 4]);
            }
#pragma unroll
            for (int nf = 0; nf < 4; nf++) {
                int n0 = wn + nf * 8 + lr;
                bf[nf][0] = f2tf32(Bs[st][n0 * GS + kb + lc    ]);
                bf[nf][1] = f2tf32(Bs[st][n0 * GS + kb + lc + 4]);
            }
#pragma unroll
            for (int mf = 0; mf < 4; mf++)
#pragma unroll
                for (int nf = 0; nf < 4; nf++)
                    MMA_TF32(c[mf][nf], af[mf], bf[nf][0], bf[nf][1]);
        }
        __syncthreads();
    }

#pragma unroll
    for (int mf = 0; mf < 4; mf++) {
#pragma unroll
        for (int nf = 0; nf < 4; nf++) {
            int row = bm + wm + mf * 16 + lr;
            int col = bn + wn + nf * 8 + lc * 2;
            *(float2*)&C[(size_t)row * N + col] =
                make_float2(c[mf][nf][0], c[mf][nf][1]);
            *(float2*)&C[(size_t)(row + 8) * N + col] =
                make_float2(c[mf][nf][2], c[mf][nf][3]);
        }
    }
}

// ============================================================
// RoPE (3-axis, interleaved pairs) + scatter to [B,H,S,Dh]
// ============================================================
__global__ void rope_scatter(const float* __restrict__ qkv,
                             const int* __restrict__ pos_xyz,
                             float* __restrict__ Q, float* __restrict__ Kb,
                             float* __restrict__ V)
{
    int idx = blockIdx.x * blockDim.x + threadIdx.x;
    if (idx >= BB * S_LEN * NH * HD) return;
    int d = idx & 63;
    int h = (idx >> 6) & 15;
    int s = (idx >> 10) & (S_LEN - 1);
    int b = idx >> 21;
    int m = b * S_LEN + s;
    const float* base = qkv + (size_t)m * (3 * DM) + h * HD;

    int axis, dim, dd;
    if (d < 20)      { axis = 0; dim = 20; dd = d; }
    else if (d < 40) { axis = 1; dim = 20; dd = d - 20; }
    else             { axis = 2; dim = 24; dd = d - 40; }
    int pair = dd >> 1;
    float pos = (float)pos_xyz[m * 3 + axis];
    float inv = expf(-logf(10000.0f) * (float)(2 * pair) / (float)dim);
    float ang = pos * inv;
    float sn, cs;
    sincosf(ang, &sn, &cs);

    float xq  = base[d];
    float xqo = (dd & 1) ? base[d - 1] : base[d + 1];
    float xk  = base[DM + d];
    float xko = (dd & 1) ? base[DM + d - 1] : base[DM + d + 1];
    float vv  = base[2 * DM + d];

    float qr = (dd & 1) ? (xq * cs + xqo * sn) : (xq * cs - xqo * sn);
    float kr = (dd & 1) ? (xk * cs + xko * sn) : (xk * cs - xko * sn);

    size_t o = ((size_t)(b * NH + h) * S_LEN + s) * HD + d;
    Q[o] = qr; Kb[o] = kr; V[o] = vv;
}

// ============================================================
// Flash attention, tf32 mma, cp.async double-buffered raw K/V.
// 64x64 tiles, 128 thr = 4 warps x 16 q-rows. 3xtf32 S-phase
// (hi/lo split computed at fragment load). Reverse-qt scheduling.
// Smem: Kraw[2][64*68], Vraw[2][64*72], Ps[4][16*76] (also Q staging).
// ============================================================
#define FS_K 68
#define FS_V 72
#define FS_PS 76
#define FA_K_WORDS (2 * 64 * FS_K)
#define FA_V_WORDS (2 * 64 * FS_V)
#define FA_PS_WORDS (4 * 16 * FS_PS)
#define FA_SMEM_BYTES ((FA_K_WORDS + FA_V_WORDS + FA_PS_WORDS) * 4)

__global__ __launch_bounds__(128, 2) void flash_attn_tf32(
    const float* __restrict__ Q, const float* __restrict__ K,
    const float* __restrict__ V, const int* __restrict__ lens,
    float* __restrict__ Out)
{
    extern __shared__ float smf[];
    float* Kraw = smf;                       // [2][64*FS_K]
    float* Vraw = smf + FA_K_WORDS;          // [2][64*FS_V]
    uint32_t* Ps = (uint32_t*)(smf + FA_K_WORDS + FA_V_WORDS);

    const int qt = (int)(gridDim.x - 1 - blockIdx.x);   // heavy CTAs first
    const int bh = blockIdx.y;
    const int b  = bh >> 4;
    const int h  = bh & 15;
    const float* Qg = Q + ((size_t)bh * S_LEN + qt * 64) * HD;
    const float* Kg = K + (size_t)bh * S_LEN * HD;
    const float* Vg = V + (size_t)bh * S_LEN * HD;
    const int klen = lens[b];

    const int tid = threadIdx.x;
    const int wq = tid >> 5;
    const int lane = tid & 31;
    const int lr = lane >> 2;
    const int lc = lane & 3;
    const int r0 = wq * 16 + lr;

    // number of valid (not fully masked) key tiles
    const int nt = min(qt + 1, (klen + 63) >> 6);

    auto issue_tile = [&](int st, int t) {
#pragma unroll
        for (int i = 0; i < 8; i++) {
            int cid = tid + i * 128;          // 0..1023
            int row = cid >> 4;
            int col = (cid & 15) * 4;
            cpa16(&Kraw[st * 64 * FS_K + row * FS_K + col],
                  &Kg[(size_t)(t * 64 + row) * HD + col]);
        }
#pragma unroll
        for (int i = 0; i < 8; i++) {
            int cid = tid + i * 128;
            int row = cid >> 4;
            int col = (cid & 15) * 4;
            cpa16(&Vraw[st * 64 * FS_V + row * FS_V + col],
                  &Vg[(size_t)(t * 64 + row) * HD + col]);
        }
        CPA_COMMIT();
    };

    if (nt > 0) issue_tile(0, 0);

    // ---- stage Q (f32) in Ps region, build persistent hi/lo frags ----
    float* Qstage = (float*)Ps;
    for (int idx = tid; idx < 64 * 16; idx += 128) {
        int q = idx >> 4, d0 = (idx & 15) << 2;
        float4 v = *(const float4*)&Qg[q * HD + d0];
        Qstage[q * FS_K + d0 + 0] = v.x;
        Qstage[q * FS_K + d0 + 1] = v.y;
        Qstage[q * FS_K + d0 + 2] = v.z;
        Qstage[q * FS_K + d0 + 3] = v.w;
    }
    __syncthreads();

    uint32_t qh[8][4], ql[8][4];
#pragma unroll
    for (int kb = 0; kb < 8; kb++) {
        float f[4];
        f[0] = Qstage[(r0    ) * FS_K + kb * 8 + lc    ];
        f[1] = Qstage[(r0 + 8) * FS_K + kb * 8 + lc    ];
        f[2] = Qstage[(r0    ) * FS_K + kb * 8 + lc + 4];
        f[3] = Qstage[(r0 + 8) * FS_K + kb * 8 + lc + 4];
#pragma unroll
        for (int i = 0; i < 4; i++) {
            qh[kb][i] = f2tf32(f[i]);
            ql[kb][i] = f2tf32(f[i] - __uint_as_float(qh[kb][i]));
        }
    }
    __syncthreads();

    float oacc[8][4];
#pragma unroll
    for (int nf = 0; nf < 8; nf++)
#pragma unroll
        for (int i = 0; i < 4; i++) oacc[nf][i] = 0.f;
    float mrow0 = -1e30f, mrow1 = -1e30f;
    float lrow0 = 0.f, lrow1 = 0.f;

    const int qg0 = qt * 64 + r0;

    for (int t = 0; t < nt; t++) {
        const int st = t & 1;
        if (t + 1 < nt) issue_tile(st ^ 1, t + 1);
        else CPA_COMMIT();
        CPA_WAIT1();
        __syncthreads();

        const float* Kt = Kraw + st * 64 * FS_K;
        const float* Vt = Vraw + st * 64 * FS_V;

        // ---- S = Q K^T (3xtf32, split K at load) ----
        float sf[8][4];
#pragma unroll
        for (int nf = 0; nf < 8; nf++)
#pragma unroll
            for (int i = 0; i < 4; i++) sf[nf][i] = 0.f;

#pragma unroll
        for (int kb = 0; kb < 8; kb++) {
#pragma unroll
            for (int nf = 0; nf < 8; nf++) {
                int n0 = nf * 8 + lr;
                float k0f = Kt[n0 * FS_K + kb * 8 + lc    ];
                float k1f = Kt[n0 * FS_K + kb * 8 + lc + 4];
                uint32_t bh0 = f2tf32(k0f), bh1 = f2tf32(k1f);
                uint32_t bl0 = f2tf32(k0f - __uint_as_float(bh0));
                uint32_t bl1 = f2tf32(k1f - __uint_as_float(bh1));
                MMA_TF32(sf[nf], qh[kb], bh0, bh1);
                MMA_TF32(sf[nf], ql[kb], bh0, bh1);
                MMA_TF32(sf[nf], qh[kb], bl0, bl1);
            }
        }

        // ---- mask + scale ----
        const bool edge = (t == qt) || ((t + 1) * 64 > klen);
#pragma unroll
        for (int nf = 0; nf < 8; nf++) {
            if (edge) {
                int kg = t * 64 + nf * 8 + lc * 2;
                sf[nf][0] = (kg     <= qg0     && kg     < klen) ? sf[nf][0] * 0.125f : -1e30f;
                sf[nf][1] = (kg + 1 <= qg0     && kg + 1 < klen) ? sf[nf][1] * 0.125f : -1e30f;
                sf[nf][2] = (kg     <= qg0 + 8 && kg     < klen) ? sf[nf][2] * 0.125f : -1e30f;
                sf[nf][3] = (kg + 1 <= qg0 + 8 && kg + 1 < klen) ? sf[nf][3] * 0.125f : -1e30f;
            } else {
                sf[nf][0] *= 0.125f; sf[nf][1] *= 0.125f;
                sf[nf][2] *= 0.125f; sf[nf][3] *= 0.125f;
            }
        }

        // ---- online softmax ----
        float m0 = -1e30f, m1 = -1e30f;
#pragma unroll
        for (int nf = 0; nf < 8; nf++) {
            m0 = fmaxf(m0, fmaxf(sf[nf][0], sf[nf][1]));
            m1 = fmaxf(m1, fmaxf(sf[nf][2], sf[nf][3]));
        }
        m0 = fmaxf(m0, __shfl_xor_sync(0xffffffffu, m0, 1));
        m0 = fmaxf(m0, __shfl_xor_sync(0xffffffffu, m0, 2));
        m1 = fmaxf(m1, __shfl_xor_sync(0xffffffffu, m1, 1));
        m1 = fmaxf(m1, __shfl_xor_sync(0xffffffffu, m1, 2));

        float mn0 = fmaxf(mrow0, m0), mn1 = fmaxf(mrow1, m1);
        float al0 = __expf(mrow0 - mn0), al1 = __expf(mrow1 - mn1);
        mrow0 = mn0; mrow1 = mn1;

        float s0 = 0.f, s1 = 0.f;
#pragma unroll
        for (int nf = 0; nf < 8; nf++) {
            float p0 = __expf(sf[nf][0] - mn0);
            float p1 = __expf(sf[nf][1] - mn0);
            float p2 = __expf(sf[nf][2] - mn1);
            float p3 = __expf(sf[nf][3] - mn1);
            sf[nf][0] = p0; sf[nf][1] = p1; sf[nf][2] = p2; sf[nf][3] = p3;
            s0 += p0 + p1; s1 += p2 + p3;
        }
        s0 += __shfl_xor_sync(0xffffffffu, s0, 1);
        s0 += __shfl_xor_sync(0xffffffffu, s0, 2);
        s1 += __shfl_xor_sync(0xffffffffu, s1, 1);
        s1 += __shfl_xor_sync(0xffffffffu, s1, 2);
        lrow0 = lrow0 * al0 + s0;
        lrow1 = lrow1 * al1 + s1;

#pragma unroll
        for (int nf = 0; nf < 8; nf++) {
            oacc[nf][0] *= al0; oacc[nf][1] *= al0;
            oacc[nf][2] *= al1; oacc[nf][3] *= al1;
        }

        // ---- store P (tf32) to warp-private smem ----
        uint32_t* PsW = Ps + wq * 16 * FS_PS;
#pragma unroll
        for (int nf = 0; nf < 8; nf++) {
            int col = nf * 8 + lc * 2;
            PsW[ lr      * FS_PS + col    ] = f2tf32(sf[nf][0]);
            PsW[ lr      * FS_PS + col + 1] = f2tf32(sf[nf][1]);
            PsW[(lr + 8) * FS_PS + col    ] = f2tf32(sf[nf][2]);
            PsW[(lr + 8) * FS_PS + col + 1] = f2tf32(sf[nf][3]);
        }
        __syncwarp();

        // ---- O += P V (V converted at load, stride-72 conflict-free) ----
#pragma unroll
        for (int kb = 0; kb < 8; kb++) {
            uint32_t af[4];
            af[0] = PsW[ lr      * FS_PS + kb * 8 + lc    ];
            af[1] = PsW[(lr + 8) * FS_PS + kb * 8 + lc    ];
            af[2] = PsW[ lr      * FS_PS + kb * 8 + lc + 4];
            af[3] = PsW[(lr + 8) * FS_PS + kb * 8 + lc + 4];
#pragma unroll
            for (int nf = 0; nf < 8; nf++) {
                int n0 = nf * 8 + lr;
                uint32_t b0 = f2tf32(Vt[(kb * 8 + lc    ) * FS_V + n0]);
                uint32_t b1 = f2tf32(Vt[(kb * 8 + lc + 4) * FS_V + n0]);
                MMA_TF32(oacc[nf], af, b0, b1);
            }
        }
        __syncthreads();
    }

    // ---- epilogue -> [B,S,H*Dh] ----
    float inv0 = 1.0f / lrow0, inv1 = 1.0f / lrow1;
#pragma unroll
    for (int nf = 0; nf < 8; nf++) {
        int col = h * HD + nf * 8 + lc * 2;
        *(float2*)&Out[((size_t)(b * S_LEN + qg0    )) * DM + col] =
            make_float2(oacc[nf][0] * inv0, oacc[nf][1] * inv0);
        *(float2*)&Out[((size_t)(b * S_LEN + qg0 + 8)) * DM + col] =
            make_float2(oacc[nf][2] * inv1, oacc[nf][3] * inv1);
    }
}

// ============================================================
extern "C" void kernel_launch(void* const* d_in, const int* in_sizes, int n_in,
                              void* d_out, int out_size)
{
    const float* hidden = (const float*)d_in[0];
    const float* w_qkv  = (const float*)d_in[1];
    const float* w_out  = (const float*)d_in[2];
    const void*  attn_mask = d_in[3];
    // d_in[4] = causal_mask (implicit)
    const int* pos_xyz = (const int*)d_in[5];
    float* out = (float*)d_out;

    float *qkv, *q, *k, *v, *ao;
    int* lens;
    cudaGetSymbolAddress((void**)&qkv,  g_qkv);
    cudaGetSymbolAddress((void**)&q,    g_q);
    cudaGetSymbolAddress((void**)&k,    g_k);
    cudaGetSymbolAddress((void**)&v,    g_v);
    cudaGetSymbolAddress((void**)&ao,   g_ao);
    cudaGetSymbolAddress((void**)&lens, g_len);

    compute_lens<<<BB, 256>>>(attn_mask);

    // 1. QKV projection (tf32, double-buffered)
    {
        dim3 grid(3 * DM / 128, M_TOK / 128);
        gemm_tf32_nt<<<grid, 256>>>(hidden, w_qkv, qkv, M_TOK, 3 * DM, DM);
    }

    // 2. RoPE + scatter
    {
        int total = BB * S_LEN * NH * HD;
        rope_scatter<<<(total + 255) / 256, 256>>>(qkv, pos_xyz, q, k, v);
    }

    // 3. Flash attention (tf32, cp.async pipelined)
    {
        cudaFuncSetAttribute(flash_attn_tf32,
                             cudaFuncAttributeMaxDynamicSharedMemorySize,
                             FA_SMEM_BYTES);
        dim3 grid(S_LEN / 64, BB * NH);
        flash_attn_tf32<<<grid, 128, FA_SMEM_BYTES>>>(q, k, v, lens, ao);
    }

    // 4. Output projection (tf32, double-buffered)
    {
        dim3 grid(DM / 128, M_TOK / 128);
        gemm_tf32_nt<<<grid, 256>>>(ao, w_out, out, M_TOK, DM, DM);
    }
}

// round 6
// speedup vs baseline: 2.4496x; 1.0841x over previous
#include <cuda_runtime.h>
#include <math.h>
#include <stdint.h>

#define S_LEN 2048
#define NH 16
#define HD 64
#define DM 1024
#define BB 2
#define M_TOK (BB * S_LEN)   // 4096

// -------- scratch (static device globals; allocation-free) --------
__device__ float g_qkv[(size_t)M_TOK * 3 * DM];
__device__ float g_q[(size_t)M_TOK * DM];        // [B,H,S,Dh] f32
__device__ uint2 g_ks[(size_t)M_TOK * DM];       // K pre-split (tf32 hi, lo)
__device__ uint32_t g_vt[(size_t)M_TOK * DM];    // V pre-converted tf32
__device__ float g_ao[(size_t)M_TOK * DM];       // attn out, [B,S,H*Dh]
__device__ int   g_len[BB];

__device__ __forceinline__ uint32_t f2tf32(float f) {
    uint32_t r;
    asm("cvt.rna.tf32.f32 %0, %1;" : "=r"(r) : "f"(f));
    return r;
}

#define MMA_TF32(c, a, b0, b1)                                              \
    asm volatile(                                                           \
        "mma.sync.aligned.m16n8k8.row.col.f32.tf32.tf32.f32 "               \
        "{%0,%1,%2,%3}, {%4,%5,%6,%7}, {%8,%9}, {%0,%1,%2,%3};"             \
        : "+f"((c)[0]), "+f"((c)[1]), "+f"((c)[2]), "+f"((c)[3])            \
        : "r"((a)[0]), "r"((a)[1]), "r"((a)[2]), "r"((a)[3]),               \
          "r"(b0), "r"(b1))

__device__ __forceinline__ void cpa16(void* smem, const void* gmem) {
    uint32_t s = (uint32_t)__cvta_generic_to_shared(smem);
    asm volatile("cp.async.cg.shared.global [%0], [%1], 16;" :: "r"(s), "l"(gmem));
}
#define CPA_COMMIT() asm volatile("cp.async.commit_group;")
#define CPA_WAIT1()  asm volatile("cp.async.wait_group 1;")
#define CPA_WAIT2()  asm volatile("cp.async.wait_group 2;")

// ============================================================
// Mask length extraction — dtype-agnostic (prefix-true mask).
// ============================================================
__global__ void compute_lens(const void* __restrict__ mask)
{
    __shared__ int cnt;
    const int b = blockIdx.x;
    if (threadIdx.x == 0) cnt = 0;
    __syncthreads();

    const unsigned char* bytes = (const unsigned char*)mask;
    int dtype;  // 0 = u8/bool, 1 = int32, 2 = float32
    if (*(const float*)mask == 1.0f) dtype = 2;
    else if (bytes[0] == 1 && bytes[1] == 0) dtype = 1;
    else dtype = 0;

    int local = 0;
    for (int s = threadIdx.x; s < S_LEN; s += blockDim.x) {
        int v;
        if (dtype == 2)      v = (((const float*)mask)[b * S_LEN + s] != 0.0f);
        else if (dtype == 1) v = (((const int*)mask)[b * S_LEN + s] != 0);
        else                 v = (bytes[b * S_LEN + s] != 0);
        local += v;
    }
    atomicAdd(&cnt, local);
    __syncthreads();
    if (threadIdx.x == 0) g_len[b] = cnt;
}

// ============================================================
// tf32 GEMM, cp.async double-buffered (unchanged from R5).
// ============================================================
#define GS 36

__global__ __launch_bounds__(256) void gemm_tf32_nt(
    const float* __restrict__ A, const float* __restrict__ B,
    float* __restrict__ C, int M, int N, int K)
{
    __shared__ float As[2][128 * GS];
    __shared__ float Bs[2][128 * GS];

    const int bm = blockIdx.y * 128;
    const int bn = blockIdx.x * 128;
    const int tid = threadIdx.x;
    const int wid = tid >> 5;
    const int lane = tid & 31;
    const int wm = (wid & 1) * 64;
    const int wn = (wid >> 1) * 32;
    const int lr = lane >> 2;
    const int lc = lane & 3;

    float c[4][4][4];
#pragma unroll
    for (int i = 0; i < 4; i++)
#pragma unroll
        for (int j = 0; j < 4; j++)
#pragma unroll
            for (int r = 0; r < 4; r++) c[i][j][r] = 0.f;

    auto issue = [&](int st, int k0) {
#pragma unroll
        for (int i = 0; i < 4; i++) {
            int cid = tid + i * 256;
            int row = cid >> 3;
            int col = (cid & 7) * 4;
            cpa16(&As[st][row * GS + col], &A[(size_t)(bm + row) * K + k0 + col]);
            cpa16(&Bs[st][row * GS + col], &B[(size_t)(bn + row) * K + k0 + col]);
        }
        CPA_COMMIT();
    };

    const int nIt = K / 32;
    issue(0, 0);

    for (int it = 0; it < nIt; it++) {
        const int st = it & 1;
        if (it + 1 < nIt) issue(st ^ 1, (it + 1) * 32);
        else CPA_COMMIT();
        CPA_WAIT1();
        __syncthreads();

#pragma unroll
        for (int ks = 0; ks < 4; ks++) {
            const int kb = ks * 8;
            uint32_t af[4][4], bf[4][2];
#pragma unroll
            for (int mf = 0; mf < 4; mf++) {
                int r0 = wm + mf * 16 + lr;
                af[mf][0] = f2tf32(As[st][(r0    ) * GS + kb + lc    ]);
                af[mf][1] = f2tf32(As[st][(r0 + 8) * GS + kb + lc    ]);
                af[mf][2] = f2tf32(As[st][(r0    ) * GS + kb + lc + 4]);
                af[mf][3] = f2tf32(As[st][(r0 + 8) * GS + kb + lc + 4]);
            }
#pragma unroll
            for (int nf = 0; nf < 4; nf++) {
                int n0 = wn + nf * 8 + lr;
                bf[nf][0] = f2tf32(Bs[st][n0 * GS + kb + lc    ]);
                bf[nf][1] = f2tf32(Bs[st][n0 * GS + kb + lc + 4]);
            }
#pragma unroll
            for (int mf = 0; mf < 4; mf++)
#pragma unroll
                for (int nf = 0; nf < 4; nf++)
                    MMA_TF32(c[mf][nf], af[mf], bf[nf][0], bf[nf][1]);
        }
        __syncthreads();
    }

#pragma unroll
    for (int mf = 0; mf < 4; mf++) {
#pragma unroll
        for (int nf = 0; nf < 4; nf++) {
            int row = bm + wm + mf * 16 + lr;
            int col = bn + wn + nf * 8 + lc * 2;
            *(float2*)&C[(size_t)row * N + col] =
                make_float2(c[mf][nf][0], c[mf][nf][1]);
            *(float2*)&C[(size_t)(row + 8) * N + col] =
                make_float2(c[mf][nf][2], c[mf][nf][3]);
        }
    }
}

// ============================================================
// RoPE + scatter. Q -> f32; K -> pre-split tf32 (hi,lo) uint2;
// V -> pre-converted tf32 u32.
// ============================================================
__global__ void rope_scatter(const float* __restrict__ qkv,
                             const int* __restrict__ pos_xyz,
                             float* __restrict__ Q, uint2* __restrict__ Ks,
                             uint32_t* __restrict__ Vt)
{
    int idx = blockIdx.x * blockDim.x + threadIdx.x;
    if (idx >= BB * S_LEN * NH * HD) return;
    int d = idx & 63;
    int h = (idx >> 6) & 15;
    int s = (idx >> 10) & (S_LEN - 1);
    int b = idx >> 21;
    int m = b * S_LEN + s;
    const float* base = qkv + (size_t)m * (3 * DM) + h * HD;

    int axis, dim, dd;
    if (d < 20)      { axis = 0; dim = 20; dd = d; }
    else if (d < 40) { axis = 1; dim = 20; dd = d - 20; }
    else             { axis = 2; dim = 24; dd = d - 40; }
    int pair = dd >> 1;
    float pos = (float)pos_xyz[m * 3 + axis];
    float inv = expf(-logf(10000.0f) * (float)(2 * pair) / (float)dim);
    float ang = pos * inv;
    float sn, cs;
    sincosf(ang, &sn, &cs);

    float xq  = base[d];
    float xqo = (dd & 1) ? base[d - 1] : base[d + 1];
    float xk  = base[DM + d];
    float xko = (dd & 1) ? base[DM + d - 1] : base[DM + d + 1];
    float vv  = base[2 * DM + d];

    float qr = (dd & 1) ? (xq * cs + xqo * sn) : (xq * cs - xqo * sn);
    float kr = (dd & 1) ? (xk * cs + xko * sn) : (xk * cs - xko * sn);

    size_t o = ((size_t)(b * NH + h) * S_LEN + s) * HD + d;
    Q[o] = qr;
    uint32_t khi = f2tf32(kr);
    uint32_t klo = f2tf32(kr - __uint_as_float(khi));
    Ks[o] = make_uint2(khi, klo);
    Vt[o] = f2tf32(vv);
}

// ============================================================
// Flash attention, tf32 mma. K pre-split (LDS.64 loads hi+lo),
// V pre-converted. K double-buffered, V single-buffered (awaited
// after softmax). 64x64 tiles, 128 thr = 4 warps.
// Smem: Ksm[2][64*68 uint2] (stride 68 uint2 = 136 words, conflict-free
// LDS.64), Vsm[64*72], Ps[4][16*76].
// ============================================================
#define FS_KU 68            // K row stride in uint2
#define FS_V 72
#define FS_PS 76
#define FA_K_WORDS (2 * 64 * FS_KU * 2)
#define FA_V_WORDS (64 * FS_V)
#define FA_PS_WORDS (4 * 16 * FS_PS)
#define FA_SMEM_BYTES ((FA_K_WORDS + FA_V_WORDS + FA_PS_WORDS) * 4)

__global__ __launch_bounds__(128, 2) void flash_attn_tf32(
    const float* __restrict__ Q, const uint2* __restrict__ K,
    const uint32_t* __restrict__ V, const int* __restrict__ lens,
    float* __restrict__ Out)
{
    extern __shared__ uint32_t smu[];
    uint2*    Ksm = (uint2*)smu;                      // [2][64*FS_KU]
    uint32_t* Vsm = smu + FA_K_WORDS;                 // [64*FS_V]
    uint32_t* Ps  = smu + FA_K_WORDS + FA_V_WORDS;    // also Q staging

    const int qt = (int)(gridDim.x - 1 - blockIdx.x);
    const int bh = blockIdx.y;
    const int b  = bh >> 4;
    const int h  = bh & 15;
    const float*    Qg = Q + ((size_t)bh * S_LEN + qt * 64) * HD;
    const uint2*    Kg = K + (size_t)bh * S_LEN * HD;
    const uint32_t* Vg = V + (size_t)bh * S_LEN * HD;
    const int klen = lens[b];

    const int tid = threadIdx.x;
    const int wq = tid >> 5;
    const int lane = tid & 31;
    const int lr = lane >> 2;
    const int lc = lane & 3;
    const int r0 = wq * 16 + lr;

    const int nt = min(qt + 1, (klen + 63) >> 6);

    // K tile: 64 rows x 64 uint2 = 32KB = 2048 x 16B chunks (16 iters)
    auto issue_K = [&](int st, int t) {
#pragma unroll
        for (int i = 0; i < 16; i++) {
            int cid = tid + i * 128;
            int row = cid >> 5;
            int ch  = (cid & 31) * 2;    // uint2 index
            cpa16(&Ksm[st * 64 * FS_KU + row * FS_KU + ch],
                  &Kg[(size_t)(t * 64 + row) * HD + ch]);
        }
    };
    // V tile: 64 rows x 64 u32 = 16KB = 1024 chunks (8 iters)
    auto issue_V = [&](int t) {
#pragma unroll
        for (int i = 0; i < 8; i++) {
            int cid = tid + i * 128;
            int row = cid >> 4;
            int col = (cid & 15) * 4;
            cpa16(&Vsm[row * FS_V + col],
                  &Vg[(size_t)(t * 64 + row) * HD + col]);
        }
    };

    issue_K(0, 0);
    CPA_COMMIT();

    // ---- stage Q (f32) in Ps region, build persistent hi/lo frags ----
    float* Qstage = (float*)Ps;
    for (int idx = tid; idx < 64 * 16; idx += 128) {
        int q = idx >> 4, d0 = (idx & 15) << 2;
        float4 v = *(const float4*)&Qg[q * HD + d0];
        Qstage[q * FS_KU + d0 + 0] = v.x;
        Qstage[q * FS_KU + d0 + 1] = v.y;
        Qstage[q * FS_KU + d0 + 2] = v.z;
        Qstage[q * FS_KU + d0 + 3] = v.w;
    }
    __syncthreads();

    uint32_t qh[8][4], ql[8][4];
#pragma unroll
    for (int kb = 0; kb < 8; kb++) {
        float f[4];
        f[0] = Qstage[(r0    ) * FS_KU + kb * 8 + lc    ];
        f[1] = Qstage[(r0 + 8) * FS_KU + kb * 8 + lc    ];
        f[2] = Qstage[(r0    ) * FS_KU + kb * 8 + lc + 4];
        f[3] = Qstage[(r0 + 8) * FS_KU + kb * 8 + lc + 4];
#pragma unroll
        for (int i = 0; i < 4; i++) {
            qh[kb][i] = f2tf32(f[i]);
            ql[kb][i] = f2tf32(f[i] - __uint_as_float(qh[kb][i]));
        }
    }
    __syncthreads();

    float oacc[8][4];
#pragma unroll
    for (int nf = 0; nf < 8; nf++)
#pragma unroll
        for (int i = 0; i < 4; i++) oacc[nf][i] = 0.f;
    float mrow0 = -1e30f, mrow1 = -1e30f;
    float lrow0 = 0.f, lrow1 = 0.f;

    const int qg0 = qt * 64 + r0;

    for (int t = 0; t < nt; t++) {
        const int st = t & 1;
        issue_V(t);
        CPA_COMMIT();
        if (t + 1 < nt) issue_K(st ^ 1, t + 1);
        CPA_COMMIT();
        // pending: K(t), V(t), K(t+1) -> wait for K(t)
        CPA_WAIT2();
        __syncthreads();

        const uint2* Kt = Ksm + st * 64 * FS_KU;

        // ---- S = Q K^T (3xtf32, pre-split K: LDS.64) ----
        float sf[8][4];
#pragma unroll
        for (int nf = 0; nf < 8; nf++)
#pragma unroll
            for (int i = 0; i < 4; i++) sf[nf][i] = 0.f;

#pragma unroll
        for (int kb = 0; kb < 8; kb++) {
#pragma unroll
            for (int nf = 0; nf < 8; nf++) {
                int n0 = nf * 8 + lr;
                uint2 k0 = Kt[n0 * FS_KU + kb * 8 + lc    ];
                uint2 k1 = Kt[n0 * FS_KU + kb * 8 + lc + 4];
                MMA_TF32(sf[nf], qh[kb], k0.x, k1.x);
                MMA_TF32(sf[nf], ql[kb], k0.x, k1.x);
                MMA_TF32(sf[nf], qh[kb], k0.y, k1.y);
            }
        }

        // ---- mask + scale ----
        const bool edge = (t == qt) || ((t + 1) * 64 > klen);
#pragma unroll
        for (int nf = 0; nf < 8; nf++) {
            if (edge) {
                int kg = t * 64 + nf * 8 + lc * 2;
                sf[nf][0] = (kg     <= qg0     && kg     < klen) ? sf[nf][0] * 0.125f : -1e30f;
                sf[nf][1] = (kg + 1 <= qg0     && kg + 1 < klen) ? sf[nf][1] * 0.125f : -1e30f;
                sf[nf][2] = (kg     <= qg0 + 8 && kg     < klen) ? sf[nf][2] * 0.125f : -1e30f;
                sf[nf][3] = (kg + 1 <= qg0 + 8 && kg + 1 < klen) ? sf[nf][3] * 0.125f : -1e30f;
            } else {
                sf[nf][0] *= 0.125f; sf[nf][1] *= 0.125f;
                sf[nf][2] *= 0.125f; sf[nf][3] *= 0.125f;
            }
        }

        // ---- online softmax ----
        float m0 = -1e30f, m1 = -1e30f;
#pragma unroll
        for (int nf = 0; nf < 8; nf++) {
            m0 = fmaxf(m0, fmaxf(sf[nf][0], sf[nf][1]));
            m1 = fmaxf(m1, fmaxf(sf[nf][2], sf[nf][3]));
        }
        m0 = fmaxf(m0, __shfl_xor_sync(0xffffffffu, m0, 1));
        m0 = fmaxf(m0, __shfl_xor_sync(0xffffffffu, m0, 2));
        m1 = fmaxf(m1, __shfl_xor_sync(0xffffffffu, m1, 1));
        m1 = fmaxf(m1, __shfl_xor_sync(0xffffffffu, m1, 2));

        float mn0 = fmaxf(mrow0, m0), mn1 = fmaxf(mrow1, m1);
        float al0 = __expf(mrow0 - mn0), al1 = __expf(mrow1 - mn1);
        mrow0 = mn0; mrow1 = mn1;

        float s0 = 0.f, s1 = 0.f;
#pragma unroll
        for (int nf = 0; nf < 8; nf++) {
            float p0 = __expf(sf[nf][0] - mn0);
            float p1 = __expf(sf[nf][1] - mn0);
            float p2 = __expf(sf[nf][2] - mn1);
            float p3 = __expf(sf[nf][3] - mn1);
            sf[nf][0] = p0; sf[nf][1] = p1; sf[nf][2] = p2; sf[nf][3] = p3;
            s0 += p0 + p1; s1 += p2 + p3;
        }
        s0 += __shfl_xor_sync(0xffffffffu, s0, 1);
        s0 += __shfl_xor_sync(0xffffffffu, s0, 2);
        s1 += __shfl_xor_sync(0xffffffffu, s1, 1);
        s1 += __shfl_xor_sync(0xffffffffu, s1, 2);
        lrow0 = lrow0 * al0 + s0;
        lrow1 = lrow1 * al1 + s1;

#pragma unroll
        for (int nf = 0; nf < 8; nf++) {
            oacc[nf][0] *= al0; oacc[nf][1] *= al0;
            oacc[nf][2] *= al1; oacc[nf][3] *= al1;
        }

        // ---- store P (tf32) to warp-private smem ----
        uint32_t* PsW = Ps + wq * 16 * FS_PS;
#pragma unroll
        for (int nf = 0; nf < 8; nf++) {
            int col = nf * 8 + lc * 2;
            PsW[ lr      * FS_PS + col    ] = f2tf32(sf[nf][0]);
            PsW[ lr      * FS_PS + col + 1] = f2tf32(sf[nf][1]);
            PsW[(lr + 8) * FS_PS + col    ] = f2tf32(sf[nf][2]);
            PsW[(lr + 8) * FS_PS + col + 1] = f2tf32(sf[nf][3]);
        }
        __syncwarp();

        // wait for V(t) (K(t+1) may still be in flight)
        CPA_WAIT1();
        __syncthreads();

        // ---- O += P V ----
#pragma unroll
        for (int kb = 0; kb < 8; kb++) {
            uint32_t af[4];
            af[0] = PsW[ lr      * FS_PS + kb * 8 + lc    ];
            af[1] = PsW[(lr + 8) * FS_PS + kb * 8 + lc    ];
            af[2] = PsW[ lr      * FS_PS + kb * 8 + lc + 4];
            af[3] = PsW[(lr + 8) * FS_PS + kb * 8 + lc + 4];
#pragma unroll
            for (int nf = 0; nf < 8; nf++) {
                int n0 = nf * 8 + lr;
                uint32_t b0 = Vsm[(kb * 8 + lc    ) * FS_V + n0];
                uint32_t b1 = Vsm[(kb * 8 + lc + 4) * FS_V + n0];
                MMA_TF32(oacc[nf], af, b0, b1);
            }
        }
        __syncthreads();   // protect Vsm before next tile's issue_V
    }

    // ---- epilogue -> [B,S,H*Dh] ----
    float inv0 = 1.0f / lrow0, inv1 = 1.0f / lrow1;
#pragma unroll
    for (int nf = 0; nf < 8; nf++) {
        int col = h * HD + nf * 8 + lc * 2;
        *(float2*)&Out[((size_t)(b * S_LEN + qg0    )) * DM + col] =
            make_float2(oacc[nf][0] * inv0, oacc[nf][1] * inv0);
        *(float2*)&Out[((size_t)(b * S_LEN + qg0 + 8)) * DM + col] =
            make_float2(oacc[nf][2] * inv1, oacc[nf][3] * inv1);
    }
}

// ============================================================
extern "C" void kernel_launch(void* const* d_in, const int* in_sizes, int n_in,
                              void* d_out, int out_size)
{
    const float* hidden = (const float*)d_in[0];
    const float* w_qkv  = (const float*)d_in[1];
    const float* w_out  = (const float*)d_in[2];
    const void*  attn_mask = d_in[3];
    // d_in[4] = causal_mask (implicit)
    const int* pos_xyz = (const int*)d_in[5];
    float* out = (float*)d_out;

    float *qkv, *q, *ao;
    uint2* ks;
    uint32_t* vt;
    int* lens;
    cudaGetSymbolAddress((void**)&qkv,  g_qkv);
    cudaGetSymbolAddress((void**)&q,    g_q);
    cudaGetSymbolAddress((void**)&ks,   g_ks);
    cudaGetSymbolAddress((void**)&vt,   g_vt);
    cudaGetSymbolAddress((void**)&ao,   g_ao);
    cudaGetSymbolAddress((void**)&lens, g_len);

    compute_lens<<<BB, 256>>>(attn_mask);

    // 1. QKV projection (tf32, double-buffered)
    {
        dim3 grid(3 * DM / 128, M_TOK / 128);
        gemm_tf32_nt<<<grid, 256>>>(hidden, w_qkv, qkv, M_TOK, 3 * DM, DM);
    }

    // 2. RoPE + scatter (K pre-split, V pre-converted)
    {
        int total = BB * S_LEN * NH * HD;
        rope_scatter<<<(total + 255) / 256, 256>>>(qkv, pos_xyz, q, ks, vt);
    }

    // 3. Flash attention
    {
        cudaFuncSetAttribute(flash_attn_tf32,
                             cudaFuncAttributeMaxDynamicSharedMemorySize,
                             FA_SMEM_BYTES);
        dim3 grid(S_LEN / 64, BB * NH);
        flash_attn_tf32<<<grid, 128, FA_SMEM_BYTES>>>(q, ks, vt, lens, ao);
    }

    // 4. Output projection (tf32, double-buffered)
    {
        dim3 grid(DM / 128, M_TOK / 128);
        gemm_tf32_nt<<<grid, 256>>>(ao, w_out, out, M_TOK, DM, DM);
    }
}

// round 7
// speedup vs baseline: 3.0824x; 1.2583x over previous
#include <cuda_runtime.h>
#include <math.h>
#include <stdint.h>

#define S_LEN 2048
#define NH 16
#define HD 64
#define DM 1024
#define BB 2
#define M_TOK (BB * S_LEN)   // 4096

// -------- scratch (static device globals; allocation-free) --------
__device__ float    g_q [(size_t)M_TOK * DM];    // [B,H,S,Dh] f32
__device__ uint32_t g_ks[(size_t)M_TOK * DM];    // K tf32 (hi)
__device__ uint32_t g_vt[(size_t)M_TOK * DM];    // V tf32
__device__ float    g_ao[(size_t)M_TOK * DM];    // attn out, [B,S,H*Dh]
__device__ int      g_len[BB];

__device__ __forceinline__ uint32_t f2tf32(float f) {
    uint32_t r;
    asm("cvt.rna.tf32.f32 %0, %1;" : "=r"(r) : "f"(f));
    return r;
}

#define MMA_TF32(c, a, b0, b1)                                              \
    asm volatile(                                                           \
        "mma.sync.aligned.m16n8k8.row.col.f32.tf32.tf32.f32 "               \
        "{%0,%1,%2,%3}, {%4,%5,%6,%7}, {%8,%9}, {%0,%1,%2,%3};"             \
        : "+f"((c)[0]), "+f"((c)[1]), "+f"((c)[2]), "+f"((c)[3])            \
        : "r"((a)[0]), "r"((a)[1]), "r"((a)[2]), "r"((a)[3]),               \
          "r"(b0), "r"(b1))

__device__ __forceinline__ void cpa16(void* smem, const void* gmem) {
    uint32_t s = (uint32_t)__cvta_generic_to_shared(smem);
    asm volatile("cp.async.cg.shared.global [%0], [%1], 16;" :: "r"(s), "l"(gmem));
}
#define CPA_COMMIT() asm volatile("cp.async.commit_group;")
#define CPA_WAIT1()  asm volatile("cp.async.wait_group 1;")
#define CPA_WAIT2()  asm volatile("cp.async.wait_group 2;")

// ============================================================
// Mask length extraction — dtype-agnostic (prefix-true mask).
// ============================================================
__global__ void compute_lens(const void* __restrict__ mask)
{
    __shared__ int cnt;
    const int b = blockIdx.x;
    if (threadIdx.x == 0) cnt = 0;
    __syncthreads();

    const unsigned char* bytes = (const unsigned char*)mask;
    int dtype;
    if (*(const float*)mask == 1.0f) dtype = 2;
    else if (bytes[0] == 1 && bytes[1] == 0) dtype = 1;
    else dtype = 0;

    int local = 0;
    for (int s = threadIdx.x; s < S_LEN; s += blockDim.x) {
        int v;
        if (dtype == 2)      v = (((const float*)mask)[b * S_LEN + s] != 0.0f);
        else if (dtype == 1) v = (((const int*)mask)[b * S_LEN + s] != 0);
        else                 v = (bytes[b * S_LEN + s] != 0);
        local += v;
    }
    atomicAdd(&cnt, local);
    __syncthreads();
    if (threadIdx.x == 0) g_len[b] = cnt;
}

// ============================================================
// Shared tf32 GEMM mainloop body (cp.async double-buffered).
// Computes the 128x128 accumulator; caller provides epilogue.
// ============================================================
#define GS 36

struct GemmCtx {
    float c[4][4][4];
    int bm, bn, wm, wn, lr, lc;
};

template <typename EPI>
__device__ __forceinline__ void gemm_tf32_body(
    const float* __restrict__ A, const float* __restrict__ B,
    int M, int N, int K, float* As /*2*128*GS*/, float* Bs, EPI epi)
{
    const int bm = blockIdx.y * 128;
    const int bn = blockIdx.x * 128;
    const int tid = threadIdx.x;
    const int wid = tid >> 5;
    const int lane = tid & 31;
    const int wm = (wid & 1) * 64;
    const int wn = (wid >> 1) * 32;
    const int lr = lane >> 2;
    const int lc = lane & 3;

    GemmCtx g;
    g.bm = bm; g.bn = bn; g.wm = wm; g.wn = wn; g.lr = lr; g.lc = lc;
#pragma unroll
    for (int i = 0; i < 4; i++)
#pragma unroll
        for (int j = 0; j < 4; j++)
#pragma unroll
            for (int r = 0; r < 4; r++) g.c[i][j][r] = 0.f;

    auto issue = [&](int st, int k0) {
#pragma unroll
        for (int i = 0; i < 4; i++) {
            int cid = tid + i * 256;
            int row = cid >> 3;
            int col = (cid & 7) * 4;
            cpa16(&As[st * 128 * GS + row * GS + col],
                  &A[(size_t)(bm + row) * K + k0 + col]);
            cpa16(&Bs[st * 128 * GS + row * GS + col],
                  &B[(size_t)(bn + row) * K + k0 + col]);
        }
        CPA_COMMIT();
    };

    const int nIt = K / 32;
    issue(0, 0);

    for (int it = 0; it < nIt; it++) {
        const int st = it & 1;
        if (it + 1 < nIt) issue(st ^ 1, (it + 1) * 32);
        else CPA_COMMIT();
        CPA_WAIT1();
        __syncthreads();

        const float* Asb = As + st * 128 * GS;
        const float* Bsb = Bs + st * 128 * GS;
#pragma unroll
        for (int ks = 0; ks < 4; ks++) {
            const int kb = ks * 8;
            uint32_t af[4][4], bf[4][2];
#pragma unroll
            for (int mf = 0; mf < 4; mf++) {
                int r0 = wm + mf * 16 + lr;
                af[mf][0] = f2tf32(Asb[(r0    ) * GS + kb + lc    ]);
                af[mf][1] = f2tf32(Asb[(r0 + 8) * GS + kb + lc    ]);
                af[mf][2] = f2tf32(Asb[(r0    ) * GS + kb + lc + 4]);
                af[mf][3] = f2tf32(Asb[(r0 + 8) * GS + kb + lc + 4]);
            }
#pragma unroll
            for (int nf = 0; nf < 4; nf++) {
                int n0 = wn + nf * 8 + lr;
                bf[nf][0] = f2tf32(Bsb[n0 * GS + kb + lc    ]);
                bf[nf][1] = f2tf32(Bsb[n0 * GS + kb + lc + 4]);
            }
#pragma unroll
            for (int mf = 0; mf < 4; mf++)
#pragma unroll
                for (int nf = 0; nf < 4; nf++)
                    MMA_TF32(g.c[mf][nf], af[mf], bf[nf][0], bf[nf][1]);
        }
        __syncthreads();
    }
    epi(g);
}

// ---- plain GEMM (out-projection) ----
__global__ __launch_bounds__(256) void gemm_tf32_nt(
    const float* __restrict__ A, const float* __restrict__ B,
    float* __restrict__ C, int M, int N, int K)
{
    __shared__ float As[2 * 128 * GS];
    __shared__ float Bs[2 * 128 * GS];
    gemm_tf32_body(A, B, M, N, K, As, Bs, [&](GemmCtx& g) {
#pragma unroll
        for (int mf = 0; mf < 4; mf++)
#pragma unroll
            for (int nf = 0; nf < 4; nf++) {
                int row = g.bm + g.wm + mf * 16 + g.lr;
                int col = g.bn + g.wn + nf * 8 + g.lc * 2;
                *(float2*)&C[(size_t)row * N + col] =
                    make_float2(g.c[mf][nf][0], g.c[mf][nf][1]);
                *(float2*)&C[(size_t)(row + 8) * N + col] =
                    make_float2(g.c[mf][nf][2], g.c[mf][nf][3]);
            }
    });
}

// ---- QKV GEMM with fused RoPE epilogue ----
// Each accumulator float2 = one RoPE pair (col even, both elems same
// axis segment since segment starts 0/20/40 are even).
__global__ __launch_bounds__(256) void gemm_qkv_rope(
    const float* __restrict__ A, const float* __restrict__ B,
    const int* __restrict__ pos_xyz,
    float* __restrict__ Q, uint32_t* __restrict__ Ks,
    uint32_t* __restrict__ Vt)
{
    __shared__ float As[2 * 128 * GS];
    __shared__ float Bs[2 * 128 * GS];
    gemm_tf32_body(A, B, M_TOK, 3 * DM, DM, As, Bs, [&](GemmCtx& g) {
        // per-nf invariants: part p, head h, dim d, axis, inv_freq
        int   pP[4], hP[4], dP[4], axP[4];
        float invP[4];
#pragma unroll
        for (int nf = 0; nf < 4; nf++) {
            int col = g.bn + g.wn + nf * 8 + g.lc * 2;
            pP[nf] = col >> 10;
            int rem = col & 1023;
            hP[nf] = rem >> 6;
            int d = rem & 63;
            dP[nf] = d;
            int axis, dim, dd;
            if (d < 20)      { axis = 0; dim = 20; dd = d; }
            else if (d < 40) { axis = 1; dim = 20; dd = d - 20; }
            else             { axis = 2; dim = 24; dd = d - 40; }
            axP[nf] = axis;
            invP[nf] = exp2f(-13.287712379549449f * (float)dd / (float)dim);
        }
#pragma unroll
        for (int mf = 0; mf < 4; mf++) {
#pragma unroll
            for (int rr = 0; rr < 2; rr++) {
                int m = g.bm + g.wm + mf * 16 + g.lr + rr * 8;
                int b = m >> 11, s = m & (S_LEN - 1);
#pragma unroll
                for (int nf = 0; nf < 4; nf++) {
                    float c0 = g.c[mf][nf][rr * 2];
                    float c1 = g.c[mf][nf][rr * 2 + 1];
                    size_t o = ((size_t)(b * NH + hP[nf]) * S_LEN + s) * HD + dP[nf];
                    if (pP[nf] == 2) {
                        Vt[o] = f2tf32(c0); Vt[o + 1] = f2tf32(c1);
                    } else {
                        float pos = (float)pos_xyz[m * 3 + axP[nf]];
                        float sn, cs;
                        sincosf(pos * invP[nf], &sn, &cs);
                        float o0 = c0 * cs - c1 * sn;
                        float o1 = c1 * cs + c0 * sn;
                        if (pP[nf] == 0) { Q[o] = o0; Q[o + 1] = o1; }
                        else { Ks[o] = f2tf32(o0); Ks[o + 1] = f2tf32(o1); }
                    }
                }
            }
        }
    });
}

// ============================================================
// Flash attention, tf32 mma, 2-term split (qh*kh + ql*kh).
// 64x64 tiles, 128 thr = 4 warps, 3 CTAs/SM target.
// Smem: Ksm[2][64*68] u32, Vsm[64*72] u32, Ps[4][16*76].
// ============================================================
#define FS_K 68
#define FS_V 72
#define FS_PS 76
#define FA_K_WORDS (2 * 64 * FS_K)
#define FA_V_WORDS (64 * FS_V)
#define FA_PS_WORDS (4 * 16 * FS_PS)
#define FA_SMEM_BYTES ((FA_K_WORDS + FA_V_WORDS + FA_PS_WORDS) * 4)

__global__ __launch_bounds__(128, 3) void flash_attn_tf32(
    const float* __restrict__ Q, const uint32_t* __restrict__ K,
    const uint32_t* __restrict__ V, const int* __restrict__ lens,
    float* __restrict__ Out)
{
    extern __shared__ uint32_t smu[];
    uint32_t* Ksm = smu;                              // [2][64*FS_K]
    uint32_t* Vsm = smu + FA_K_WORDS;                 // [64*FS_V]
    uint32_t* Ps  = smu + FA_K_WORDS + FA_V_WORDS;    // also Q staging

    const int qt = (int)(gridDim.x - 1 - blockIdx.x);
    const int bh = blockIdx.y;
    const int b  = bh >> 4;
    const int h  = bh & 15;
    const float*    Qg = Q + ((size_t)bh * S_LEN + qt * 64) * HD;
    const uint32_t* Kg = K + (size_t)bh * S_LEN * HD;
    const uint32_t* Vg = V + (size_t)bh * S_LEN * HD;
    const int klen = lens[b];

    const int tid = threadIdx.x;
    const int wq = tid >> 5;
    const int lane = tid & 31;
    const int lr = lane >> 2;
    const int lc = lane & 3;
    const int r0 = wq * 16 + lr;

    const int nt = min(qt + 1, (klen + 63) >> 6);

    auto issue_K = [&](int st, int t) {
#pragma unroll
        for (int i = 0; i < 8; i++) {
            int cid = tid + i * 128;
            int row = cid >> 4;
            int col = (cid & 15) * 4;
            cpa16(&Ksm[st * 64 * FS_K + row * FS_K + col],
                  &Kg[(size_t)(t * 64 + row) * HD + col]);
        }
    };
    auto issue_V = [&](int t) {
#pragma unroll
        for (int i = 0; i < 8; i++) {
            int cid = tid + i * 128;
            int row = cid >> 4;
            int col = (cid & 15) * 4;
            cpa16(&Vsm[row * FS_V + col],
                  &Vg[(size_t)(t * 64 + row) * HD + col]);
        }
    };

    issue_K(0, 0);
    CPA_COMMIT();

    // ---- stage Q, build persistent hi/lo fragments ----
    float* Qstage = (float*)Ps;
    for (int idx = tid; idx < 64 * 16; idx += 128) {
        int q = idx >> 4, d0 = (idx & 15) << 2;
        float4 v = *(const float4*)&Qg[q * HD + d0];
        Qstage[q * FS_K + d0 + 0] = v.x;
        Qstage[q * FS_K + d0 + 1] = v.y;
        Qstage[q * FS_K + d0 + 2] = v.z;
        Qstage[q * FS_K + d0 + 3] = v.w;
    }
    __syncthreads();

    uint32_t qh[8][4], ql[8][4];
#pragma unroll
    for (int kb = 0; kb < 8; kb++) {
        float f[4];
        f[0] = Qstage[(r0    ) * FS_K + kb * 8 + lc    ];
        f[1] = Qstage[(r0 + 8) * FS_K + kb * 8 + lc    ];
        f[2] = Qstage[(r0    ) * FS_K + kb * 8 + lc + 4];
        f[3] = Qstage[(r0 + 8) * FS_K + kb * 8 + lc + 4];
#pragma unroll
        for (int i = 0; i < 4; i++) {
            qh[kb][i] = f2tf32(f[i]);
            ql[kb][i] = f2tf32(f[i] - __uint_as_float(qh[kb][i]));
        }
    }
    __syncthreads();

    float oacc[8][4];
#pragma unroll
    for (int nf = 0; nf < 8; nf++)
#pragma unroll
        for (int i = 0; i < 4; i++) oacc[nf][i] = 0.f;
    float mrow0 = -1e30f, mrow1 = -1e30f;
    float lrow0 = 0.f, lrow1 = 0.f;

    const int qg0 = qt * 64 + r0;

    for (int t = 0; t < nt; t++) {
        const int st = t & 1;
        issue_V(t);
        CPA_COMMIT();
        if (t + 1 < nt) issue_K(st ^ 1, t + 1);
        CPA_COMMIT();
        CPA_WAIT2();          // K(t) ready
        __syncthreads();

        const uint32_t* Kt = Ksm + st * 64 * FS_K;

        // ---- S = Q K^T (2-term split: qh*kh + ql*kh) ----
        float sf[8][4];
#pragma unroll
        for (int nf = 0; nf < 8; nf++)
#pragma unroll
            for (int i = 0; i < 4; i++) sf[nf][i] = 0.f;

#pragma unroll
        for (int kb = 0; kb < 8; kb++) {
#pragma unroll
            for (int nf = 0; nf < 8; nf++) {
                int n0 = nf * 8 + lr;
                uint32_t k0 = Kt[n0 * FS_K + kb * 8 + lc    ];
                uint32_t k1 = Kt[n0 * FS_K + kb * 8 + lc + 4];
                MMA_TF32(sf[nf], qh[kb], k0, k1);
                MMA_TF32(sf[nf], ql[kb], k0, k1);
            }
        }

        // ---- mask + scale ----
        const bool edge = (t == qt) || ((t + 1) * 64 > klen);
#pragma unroll
        for (int nf = 0; nf < 8; nf++) {
            if (edge) {
                int kg = t * 64 + nf * 8 + lc * 2;
                sf[nf][0] = (kg     <= qg0     && kg     < klen) ? sf[nf][0] * 0.125f : -1e30f;
                sf[nf][1] = (kg + 1 <= qg0     && kg + 1 < klen) ? sf[nf][1] * 0.125f : -1e30f;
                sf[nf][2] = (kg     <= qg0 + 8 && kg     < klen) ? sf[nf][2] * 0.125f : -1e30f;
                sf[nf][3] = (kg + 1 <= qg0 + 8 && kg + 1 < klen) ? sf[nf][3] * 0.125f : -1e30f;
            } else {
                sf[nf][0] *= 0.125f; sf[nf][1] *= 0.125f;
                sf[nf][2] *= 0.125f; sf[nf][3] *= 0.125f;
            }
        }

        // ---- online softmax ----
        float m0 = -1e30f, m1 = -1e30f;
#pragma unroll
        for (int nf = 0; nf < 8; nf++) {
            m0 = fmaxf(m0, fmaxf(sf[nf][0], sf[nf][1]));
            m1 = fmaxf(m1, fmaxf(sf[nf][2], sf[nf][3]));
        }
        m0 = fmaxf(m0, __shfl_xor_sync(0xffffffffu, m0, 1));
        m0 = fmaxf(m0, __shfl_xor_sync(0xffffffffu, m0, 2));
        m1 = fmaxf(m1, __shfl_xor_sync(0xffffffffu, m1, 1));
        m1 = fmaxf(m1, __shfl_xor_sync(0xffffffffu, m1, 2));

        float mn0 = fmaxf(mrow0, m0), mn1 = fmaxf(mrow1, m1);
        float al0 = __expf(mrow0 - mn0), al1 = __expf(mrow1 - mn1);
        mrow0 = mn0; mrow1 = mn1;

        float s0 = 0.f, s1 = 0.f;
#pragma unroll
        for (int nf = 0; nf < 8; nf++) {
            float p0 = __expf(sf[nf][0] - mn0);
            float p1 = __expf(sf[nf][1] - mn0);
            float p2 = __expf(sf[nf][2] - mn1);
            float p3 = __expf(sf[nf][3] - mn1);
            sf[nf][0] = p0; sf[nf][1] = p1; sf[nf][2] = p2; sf[nf][3] = p3;
            s0 += p0 + p1; s1 += p2 + p3;
        }
        s0 += __shfl_xor_sync(0xffffffffu, s0, 1);
        s0 += __shfl_xor_sync(0xffffffffu, s0, 2);
        s1 += __shfl_xor_sync(0xffffffffu, s1, 1);
        s1 += __shfl_xor_sync(0xffffffffu, s1, 2);
        lrow0 = lrow0 * al0 + s0;
        lrow1 = lrow1 * al1 + s1;

#pragma unroll
        for (int nf = 0; nf < 8; nf++) {
            oacc[nf][0] *= al0; oacc[nf][1] *= al0;
            oacc[nf][2] *= al1; oacc[nf][3] *= al1;
        }

        // ---- store P (tf32) to warp-private smem ----
        uint32_t* PsW = Ps + wq * 16 * FS_PS;
#pragma unroll
        for (int nf = 0; nf < 8; nf++) {
            int col = nf * 8 + lc * 2;
            PsW[ lr      * FS_PS + col    ] = f2tf32(sf[nf][0]);
            PsW[ lr      * FS_PS + col + 1] = f2tf32(sf[nf][1]);
            PsW[(lr + 8) * FS_PS + col    ] = f2tf32(sf[nf][2]);
            PsW[(lr + 8) * FS_PS + col + 1] = f2tf32(sf[nf][3]);
        }
        __syncwarp();

        CPA_WAIT1();          // V(t) ready
        __syncthreads();

        // ---- O += P V ----
#pragma unroll
        for (int kb = 0; kb < 8; kb++) {
            uint32_t af[4];
            af[0] = PsW[ lr      * FS_PS + kb * 8 + lc    ];
            af[1] = PsW[(lr + 8) * FS_PS + kb * 8 + lc    ];
            af[2] = PsW[ lr      * FS_PS + kb * 8 + lc + 4];
            af[3] = PsW[(lr + 8) * FS_PS + kb * 8 + lc + 4];
#pragma unroll
            for (int nf = 0; nf < 8; nf++) {
                int n0 = nf * 8 + lr;
                uint32_t b0 = Vsm[(kb * 8 + lc    ) * FS_V + n0];
                uint32_t b1 = Vsm[(kb * 8 + lc + 4) * FS_V + n0];
                MMA_TF32(oacc[nf], af, b0, b1);
            }
        }
        __syncthreads();
    }

    // ---- epilogue -> [B,S,H*Dh] ----
    float inv0 = 1.0f / lrow0, inv1 = 1.0f / lrow1;
#pragma unroll
    for (int nf = 0; nf < 8; nf++) {
        int col = h * HD + nf * 8 + lc * 2;
        *(float2*)&Out[((size_t)(b * S_LEN + qg0    )) * DM + col] =
            make_float2(oacc[nf][0] * inv0, oacc[nf][1] * inv0);
        *(float2*)&Out[((size_t)(b * S_LEN + qg0 + 8)) * DM + col] =
            make_float2(oacc[nf][2] * inv1, oacc[nf][3] * inv1);
    }
}

// ============================================================
extern "C" void kernel_launch(void* const* d_in, const int* in_sizes, int n_in,
                              void* d_out, int out_size)
{
    const float* hidden = (const float*)d_in[0];
    const float* w_qkv  = (const float*)d_in[1];
    const float* w_out  = (const float*)d_in[2];
    const void*  attn_mask = d_in[3];
    // d_in[4] = causal_mask (implicit)
    const int* pos_xyz = (const int*)d_in[5];
    float* out = (float*)d_out;

    float *q, *ao;
    uint32_t *ks, *vt;
    int* lens;
    cudaGetSymbolAddress((void**)&q,    g_q);
    cudaGetSymbolAddress((void**)&ks,   g_ks);
    cudaGetSymbolAddress((void**)&vt,   g_vt);
    cudaGetSymbolAddress((void**)&ao,   g_ao);
    cudaGetSymbolAddress((void**)&lens, g_len);

    compute_lens<<<BB, 256>>>(attn_mask);

    // 1. QKV projection + fused RoPE/scatter
    {
        dim3 grid(3 * DM / 128, M_TOK / 128);
        gemm_qkv_rope<<<grid, 256>>>(hidden, w_qkv, pos_xyz, q, ks, vt);
    }

    // 2. Flash attention (2-term tf32 split, 3 CTAs/SM)
    {
        cudaFuncSetAttribute(flash_attn_tf32,
                             cudaFuncAttributeMaxDynamicSharedMemorySize,
                             FA_SMEM_BYTES);
        dim3 grid(S_LEN / 64, BB * NH);
        flash_attn_tf32<<<grid, 128, FA_SMEM_BYTES>>>(q, ks, vt, lens, ao);
    }

    // 3. Output projection
    {
        dim3 grid(DM / 128, M_TOK / 128);
        gemm_tf32_nt<<<grid, 256>>>(ao, w_out, out, M_TOK, DM, DM);
    }
}

// round 8
// speedup vs baseline: 3.1466x; 1.0208x over previous
#include <cuda_runtime.h>
#include <math.h>
#include <stdint.h>

#define S_LEN 2048
#define NH 16
#define HD 64
#define DM 1024
#define BB 2
#define M_TOK (BB * S_LEN)   // 4096

// -------- scratch (static device globals; allocation-free) --------
__device__ uint32_t g_hid_p[(size_t)M_TOK * DM];     // hidden, tf32 paired
__device__ uint32_t g_wqkv_p[(size_t)3 * DM * DM];   // w_qkv, tf32 paired
__device__ uint32_t g_wout_p[(size_t)DM * DM];       // w_out, tf32 paired
__device__ float    g_q [(size_t)M_TOK * DM];        // [B,H,S,Dh] f32
__device__ uint32_t g_ks[(size_t)M_TOK * DM];        // K tf32 (hi)
__device__ uint32_t g_vt[(size_t)M_TOK * DM];        // V tf32
__device__ uint32_t g_ao[(size_t)M_TOK * DM];        // attn out, tf32 paired
__device__ int      g_len[BB];

__device__ __forceinline__ uint32_t f2tf32(float f) {
    uint32_t r;
    asm("cvt.rna.tf32.f32 %0, %1;" : "=r"(r) : "f"(f));
    return r;
}

#define MMA_TF32(c, a, b0, b1)                                              \
    asm volatile(                                                           \
        "mma.sync.aligned.m16n8k8.row.col.f32.tf32.tf32.f32 "               \
        "{%0,%1,%2,%3}, {%4,%5,%6,%7}, {%8,%9}, {%0,%1,%2,%3};"             \
        : "+f"((c)[0]), "+f"((c)[1]), "+f"((c)[2]), "+f"((c)[3])            \
        : "r"((a)[0]), "r"((a)[1]), "r"((a)[2]), "r"((a)[3]),               \
          "r"(b0), "r"(b1))

__device__ __forceinline__ void cpa16(void* smem, const void* gmem) {
    uint32_t s = (uint32_t)__cvta_generic_to_shared(smem);
    asm volatile("cp.async.cg.shared.global [%0], [%1], 16;" :: "r"(s), "l"(gmem));
}
#define CPA_COMMIT() asm volatile("cp.async.commit_group;")
#define CPA_WAIT1()  asm volatile("cp.async.wait_group 1;")
#define CPA_WAIT2()  asm volatile("cp.async.wait_group 2;")

// ============================================================
// Mask length extraction — dtype-agnostic (prefix-true mask).
// ============================================================
__global__ void compute_lens(const void* __restrict__ mask)
{
    __shared__ int cnt;
    const int b = blockIdx.x;
    if (threadIdx.x == 0) cnt = 0;
    __syncthreads();

    const unsigned char* bytes = (const unsigned char*)mask;
    int dtype;
    if (*(const float*)mask == 1.0f) dtype = 2;
    else if (bytes[0] == 1 && bytes[1] == 0) dtype = 1;
    else dtype = 0;

    int local = 0;
    for (int s = threadIdx.x; s < S_LEN; s += blockDim.x) {
        int v;
        if (dtype == 2)      v = (((const float*)mask)[b * S_LEN + s] != 0.0f);
        else if (dtype == 1) v = (((const int*)mask)[b * S_LEN + s] != 0);
        else                 v = (bytes[b * S_LEN + s] != 0);
        local += v;
    }
    atomicAdd(&cnt, local);
    __syncthreads();
    if (threadIdx.x == 0) g_len[b] = cnt;
}

// ============================================================
// Convert f32 -> tf32 with K-pair interleave: within each 8-col
// block, output slot p takes source col (p even: p/2, p odd: p/2+4).
// ============================================================
__global__ void cvt_pair(const float* __restrict__ in,
                         uint32_t* __restrict__ out, int n)
{
    int idx = blockIdx.x * blockDim.x + threadIdx.x;
    if (idx >= n) return;
    int blk = idx >> 3, p = idx & 7;
    int c = (p & 1) ? ((p >> 1) + 4) : (p >> 1);
    out[idx] = f2tf32(in[(size_t)blk * 8 + c]);
}

// ============================================================
// Paired-tf32 GEMM body: C[m,n] = sum_k A[m,k]*B[n,k], A/B in
// paired-tf32 u32 layout. 128x128 tile, BK=32 (16 uint2/row).
// smem row stride 20 uint2 -> conflict-free LDS.64 fragments.
// ============================================================
#define GSP 20   // uint2 per smem row

struct GemmCtx {
    float c[4][4][4];
    int bm, bn, wm, wn, lr, lc;
};

template <typename EPI>
__device__ __forceinline__ void gemm_tf32p_body(
    const uint32_t* __restrict__ A, const uint32_t* __restrict__ B,
    int M, int N, int K, uint2* As, uint2* Bs, EPI epi)
{
    const int bm = blockIdx.y * 128;
    const int bn = blockIdx.x * 128;
    const int tid = threadIdx.x;
    const int wid = tid >> 5;
    const int lane = tid & 31;
    const int wm = (wid & 1) * 64;
    const int wn = (wid >> 1) * 32;
    const int lr = lane >> 2;
    const int lc = lane & 3;

    GemmCtx g;
    g.bm = bm; g.bn = bn; g.wm = wm; g.wn = wn; g.lr = lr; g.lc = lc;
#pragma unroll
    for (int i = 0; i < 4; i++)
#pragma unroll
        for (int j = 0; j < 4; j++)
#pragma unroll
            for (int r = 0; r < 4; r++) g.c[i][j][r] = 0.f;

    auto issue = [&](int st, int k0 /*u32 units*/) {
#pragma unroll
        for (int i = 0; i < 4; i++) {
            int cid = tid + i * 256;          // 0..1023
            int row = cid >> 3;
            int cc  = (cid & 7) * 2;          // uint2 col
            cpa16(&As[st * 128 * GSP + row * GSP + cc],
                  &A[(size_t)(bm + row) * K + k0 + cc * 2]);
            cpa16(&Bs[st * 128 * GSP + row * GSP + cc],
                  &B[(size_t)(bn + row) * K + k0 + cc * 2]);
        }
        CPA_COMMIT();
    };

    const int nIt = K / 32;
    issue(0, 0);

    for (int it = 0; it < nIt; it++) {
        const int st = it & 1;
        if (it + 1 < nIt) issue(st ^ 1, (it + 1) * 32);
        else CPA_COMMIT();
        CPA_WAIT1();
        __syncthreads();

        const uint2* Asb = As + st * 128 * GSP;
        const uint2* Bsb = Bs + st * 128 * GSP;
#pragma unroll
        for (int ks = 0; ks < 4; ks++) {
            uint32_t af[4][4], bf[4][2];
#pragma unroll
            for (int mf = 0; mf < 4; mf++) {
                int r0 = wm + mf * 16 + lr;
                uint2 x = Asb[(r0    ) * GSP + ks * 4 + lc];
                uint2 y = Asb[(r0 + 8) * GSP + ks * 4 + lc];
                af[mf][0] = x.x; af[mf][1] = y.x;
                af[mf][2] = x.y; af[mf][3] = y.y;
            }
#pragma unroll
            for (int nf = 0; nf < 4; nf++) {
                uint2 z = Bsb[(wn + nf * 8 + lr) * GSP + ks * 4 + lc];
                bf[nf][0] = z.x; bf[nf][1] = z.y;
            }
#pragma unroll
            for (int mf = 0; mf < 4; mf++)
#pragma unroll
                for (int nf = 0; nf < 4; nf++)
                    MMA_TF32(g.c[mf][nf], af[mf], bf[nf][0], bf[nf][1]);
        }
        __syncthreads();
    }
    epi(g);
}

// ---- out-projection ----
__global__ __launch_bounds__(256) void gemm_out(
    const uint32_t* __restrict__ A, const uint32_t* __restrict__ B,
    float* __restrict__ C, int M, int N, int K)
{
    __shared__ uint2 As[2 * 128 * GSP];
    __shared__ uint2 Bs[2 * 128 * GSP];
    gemm_tf32p_body(A, B, M, N, K, As, Bs, [&](GemmCtx& g) {
#pragma unroll
        for (int mf = 0; mf < 4; mf++)
#pragma unroll
            for (int nf = 0; nf < 4; nf++) {
                int row = g.bm + g.wm + mf * 16 + g.lr;
                int col = g.bn + g.wn + nf * 8 + g.lc * 2;
                *(float2*)&C[(size_t)row * N + col] =
                    make_float2(g.c[mf][nf][0], g.c[mf][nf][1]);
                *(float2*)&C[(size_t)(row + 8) * N + col] =
                    make_float2(g.c[mf][nf][2], g.c[mf][nf][3]);
            }
    });
}

// ---- QKV GEMM with fused RoPE epilogue ----
__global__ __launch_bounds__(256) void gemm_qkv_rope(
    const uint32_t* __restrict__ A, const uint32_t* __restrict__ B,
    const int* __restrict__ pos_xyz,
    float* __restrict__ Q, uint32_t* __restrict__ Ks,
    uint32_t* __restrict__ Vt)
{
    __shared__ uint2 As[2 * 128 * GSP];
    __shared__ uint2 Bs[2 * 128 * GSP];
    gemm_tf32p_body(A, B, M_TOK, 3 * DM, DM, As, Bs, [&](GemmCtx& g) {
        int   pP[4], hP[4], dP[4], axP[4];
        float invP[4];
#pragma unroll
        for (int nf = 0; nf < 4; nf++) {
            int col = g.bn + g.wn + nf * 8 + g.lc * 2;
            pP[nf] = col >> 10;
            int rem = col & 1023;
            hP[nf] = rem >> 6;
            int d = rem & 63;
            dP[nf] = d;
            int axis, dim, dd;
            if (d < 20)      { axis = 0; dim = 20; dd = d; }
            else if (d < 40) { axis = 1; dim = 20; dd = d - 20; }
            else             { axis = 2; dim = 24; dd = d - 40; }
            axP[nf] = axis;
            invP[nf] = exp2f(-13.287712379549449f * (float)dd / (float)dim);
        }
#pragma unroll
        for (int mf = 0; mf < 4; mf++) {
#pragma unroll
            for (int rr = 0; rr < 2; rr++) {
                int m = g.bm + g.wm + mf * 16 + g.lr + rr * 8;
                int b = m >> 11, s = m & (S_LEN - 1);
#pragma unroll
                for (int nf = 0; nf < 4; nf++) {
                    float c0 = g.c[mf][nf][rr * 2];
                    float c1 = g.c[mf][nf][rr * 2 + 1];
                    size_t o = ((size_t)(b * NH + hP[nf]) * S_LEN + s) * HD + dP[nf];
                    if (pP[nf] == 2) {
                        Vt[o] = f2tf32(c0); Vt[o + 1] = f2tf32(c1);
                    } else {
                        float pos = (float)pos_xyz[m * 3 + axP[nf]];
                        float sn, cs;
                        sincosf(pos * invP[nf], &sn, &cs);
                        float o0 = c0 * cs - c1 * sn;
                        float o1 = c1 * cs + c0 * sn;
                        if (pP[nf] == 0) { Q[o] = o0; Q[o + 1] = o1; }
                        else { Ks[o] = f2tf32(o0); Ks[o + 1] = f2tf32(o1); }
                    }
                }
            }
        }
    });
}

// ============================================================
// Flash attention (unchanged mainloop from R7; epilogue writes
// attention output as PAIRED tf32 for the out-projection).
// ============================================================
#define FS_K 68
#define FS_V 72
#define FS_PS 76
#define FA_K_WORDS (2 * 64 * FS_K)
#define FA_V_WORDS (64 * FS_V)
#define FA_PS_WORDS (4 * 16 * FS_PS)
#define FA_SMEM_BYTES ((FA_K_WORDS + FA_V_WORDS + FA_PS_WORDS) * 4)

__global__ __launch_bounds__(128, 3) void flash_attn_tf32(
    const float* __restrict__ Q, const uint32_t* __restrict__ K,
    const uint32_t* __restrict__ V, const int* __restrict__ lens,
    uint32_t* __restrict__ Out)
{
    extern __shared__ uint32_t smu[];
    uint32_t* Ksm = smu;
    uint32_t* Vsm = smu + FA_K_WORDS;
    uint32_t* Ps  = smu + FA_K_WORDS + FA_V_WORDS;

    const int qt = (int)(gridDim.x - 1 - blockIdx.x);
    const int bh = blockIdx.y;
    const int b  = bh >> 4;
    const int h  = bh & 15;
    const float*    Qg = Q + ((size_t)bh * S_LEN + qt * 64) * HD;
    const uint32_t* Kg = K + (size_t)bh * S_LEN * HD;
    const uint32_t* Vg = V + (size_t)bh * S_LEN * HD;
    const int klen = lens[b];

    const int tid = threadIdx.x;
    const int wq = tid >> 5;
    const int lane = tid & 31;
    const int lr = lane >> 2;
    const int lc = lane & 3;
    const int r0 = wq * 16 + lr;

    const int nt = min(qt + 1, (klen + 63) >> 6);

    auto issue_K = [&](int st, int t) {
#pragma unroll
        for (int i = 0; i < 8; i++) {
            int cid = tid + i * 128;
            int row = cid >> 4;
            int col = (cid & 15) * 4;
            cpa16(&Ksm[st * 64 * FS_K + row * FS_K + col],
                  &Kg[(size_t)(t * 64 + row) * HD + col]);
        }
    };
    auto issue_V = [&](int t) {
#pragma unroll
        for (int i = 0; i < 8; i++) {
            int cid = tid + i * 128;
            int row = cid >> 4;
            int col = (cid & 15) * 4;
            cpa16(&Vsm[row * FS_V + col],
                  &Vg[(size_t)(t * 64 + row) * HD + col]);
        }
    };

    issue_K(0, 0);
    CPA_COMMIT();

    float* Qstage = (float*)Ps;
    for (int idx = tid; idx < 64 * 16; idx += 128) {
        int q = idx >> 4, d0 = (idx & 15) << 2;
        float4 v = *(const float4*)&Qg[q * HD + d0];
        Qstage[q * FS_K + d0 + 0] = v.x;
        Qstage[q * FS_K + d0 + 1] = v.y;
        Qstage[q * FS_K + d0 + 2] = v.z;
        Qstage[q * FS_K + d0 + 3] = v.w;
    }
    __syncthreads();

    uint32_t qh[8][4], ql[8][4];
#pragma unroll
    for (int kb = 0; kb < 8; kb++) {
        float f[4];
        f[0] = Qstage[(r0    ) * FS_K + kb * 8 + lc    ];
        f[1] = Qstage[(r0 + 8) * FS_K + kb * 8 + lc    ];
        f[2] = Qstage[(r0    ) * FS_K + kb * 8 + lc + 4];
        f[3] = Qstage[(r0 + 8) * FS_K + kb * 8 + lc + 4];
#pragma unroll
        for (int i = 0; i < 4; i++) {
            qh[kb][i] = f2tf32(f[i]);
            ql[kb][i] = f2tf32(f[i] - __uint_as_float(qh[kb][i]));
        }
    }
    __syncthreads();

    float oacc[8][4];
#pragma unroll
    for (int nf = 0; nf < 8; nf++)
#pragma unroll
        for (int i = 0; i < 4; i++) oacc[nf][i] = 0.f;
    float mrow0 = -1e30f, mrow1 = -1e30f;
    float lrow0 = 0.f, lrow1 = 0.f;

    const int qg0 = qt * 64 + r0;

    for (int t = 0; t < nt; t++) {
        const int st = t & 1;
        issue_V(t);
        CPA_COMMIT();
        if (t + 1 < nt) issue_K(st ^ 1, t + 1);
        CPA_COMMIT();
        CPA_WAIT2();
        __syncthreads();

        const uint32_t* Kt = Ksm + st * 64 * FS_K;

        float sf[8][4];
#pragma unroll
        for (int nf = 0; nf < 8; nf++)
#pragma unroll
            for (int i = 0; i < 4; i++) sf[nf][i] = 0.f;

#pragma unroll
        for (int kb = 0; kb < 8; kb++) {
#pragma unroll
            for (int nf = 0; nf < 8; nf++) {
                int n0 = nf * 8 + lr;
                uint32_t k0 = Kt[n0 * FS_K + kb * 8 + lc    ];
                uint32_t k1 = Kt[n0 * FS_K + kb * 8 + lc + 4];
                MMA_TF32(sf[nf], qh[kb], k0, k1);
                MMA_TF32(sf[nf], ql[kb], k0, k1);
            }
        }

        const bool edge = (t == qt) || ((t + 1) * 64 > klen);
#pragma unroll
        for (int nf = 0; nf < 8; nf++) {
            if (edge) {
                int kg = t * 64 + nf * 8 + lc * 2;
                sf[nf][0] = (kg     <= qg0     && kg     < klen) ? sf[nf][0] * 0.125f : -1e30f;
                sf[nf][1] = (kg + 1 <= qg0     && kg + 1 < klen) ? sf[nf][1] * 0.125f : -1e30f;
                sf[nf][2] = (kg     <= qg0 + 8 && kg     < klen) ? sf[nf][2] * 0.125f : -1e30f;
                sf[nf][3] = (kg + 1 <= qg0 + 8 && kg + 1 < klen) ? sf[nf][3] * 0.125f : -1e30f;
            } else {
                sf[nf][0] *= 0.125f; sf[nf][1] *= 0.125f;
                sf[nf][2] *= 0.125f; sf[nf][3] *= 0.125f;
            }
        }

        float m0 = -1e30f, m1 = -1e30f;
#pragma unroll
        for (int nf = 0; nf < 8; nf++) {
            m0 = fmaxf(m0, fmaxf(sf[nf][0], sf[nf][1]));
            m1 = fmaxf(m1, fmaxf(sf[nf][2], sf[nf][3]));
        }
        m0 = fmaxf(m0, __shfl_xor_sync(0xffffffffu, m0, 1));
        m0 = fmaxf(m0, __shfl_xor_sync(0xffffffffu, m0, 2));
        m1 = fmaxf(m1, __shfl_xor_sync(0xffffffffu, m1, 1));
        m1 = fmaxf(m1, __shfl_xor_sync(0xffffffffu, m1, 2));

        float mn0 = fmaxf(mrow0, m0), mn1 = fmaxf(mrow1, m1);
        float al0 = __expf(mrow0 - mn0), al1 = __expf(mrow1 - mn1);
        mrow0 = mn0; mrow1 = mn1;

        float s0 = 0.f, s1 = 0.f;
#pragma unroll
        for (int nf = 0; nf < 8; nf++) {
            float p0 = __expf(sf[nf][0] - mn0);
            float p1 = __expf(sf[nf][1] - mn0);
            float p2 = __expf(sf[nf][2] - mn1);
            float p3 = __expf(sf[nf][3] - mn1);
            sf[nf][0] = p0; sf[nf][1] = p1; sf[nf][2] = p2; sf[nf][3] = p3;
            s0 += p0 + p1; s1 += p2 + p3;
        }
        s0 += __shfl_xor_sync(0xffffffffu, s0, 1);
        s0 += __shfl_xor_sync(0xffffffffu, s0, 2);
        s1 += __shfl_xor_sync(0xffffffffu, s1, 1);
        s1 += __shfl_xor_sync(0xffffffffu, s1, 2);
        lrow0 = lrow0 * al0 + s0;
        lrow1 = lrow1 * al1 + s1;

#pragma unroll
        for (int nf = 0; nf < 8; nf++) {
            oacc[nf][0] *= al0; oacc[nf][1] *= al0;
            oacc[nf][2] *= al1; oacc[nf][3] *= al1;
        }

        uint32_t* PsW = Ps + wq * 16 * FS_PS;
#pragma unroll
        for (int nf = 0; nf < 8; nf++) {
            int col = nf * 8 + lc * 2;
            PsW[ lr      * FS_PS + col    ] = f2tf32(sf[nf][0]);
            PsW[ lr      * FS_PS + col + 1] = f2tf32(sf[nf][1]);
            PsW[(lr + 8) * FS_PS + col    ] = f2tf32(sf[nf][2]);
            PsW[(lr + 8) * FS_PS + col + 1] = f2tf32(sf[nf][3]);
        }
        __syncwarp();

        CPA_WAIT1();
        __syncthreads();

#pragma unroll
        for (int kb = 0; kb < 8; kb++) {
            uint32_t af[4];
            af[0] = PsW[ lr      * FS_PS + kb * 8 + lc    ];
            af[1] = PsW[(lr + 8) * FS_PS + kb * 8 + lc    ];
            af[2] = PsW[ lr      * FS_PS + kb * 8 + lc + 4];
            af[3] = PsW[(lr + 8) * FS_PS + kb * 8 + lc + 4];
#pragma unroll
            for (int nf = 0; nf < 8; nf++) {
                int n0 = nf * 8 + lr;
                uint32_t b0 = Vsm[(kb * 8 + lc    ) * FS_V + n0];
                uint32_t b1 = Vsm[(kb * 8 + lc + 4) * FS_V + n0];
                MMA_TF32(oacc[nf], af, b0, b1);
            }
        }
        __syncthreads();
    }

    // ---- epilogue -> attention out as PAIRED tf32 [B,S,H*Dh] ----
    // within 8-block, cols (2lc, 2lc+1) -> paired slots (pos0, pos0+2)
    const int pos0 = ((lc & 1) << 2) + (lc >> 1);
    float inv0 = 1.0f / lrow0, inv1 = 1.0f / lrow1;
#pragma unroll
    for (int nf = 0; nf < 8; nf++) {
        int base = h * HD + nf * 8;
        size_t ro0 = ((size_t)(b * S_LEN + qg0    )) * DM + base;
        size_t ro1 = ((size_t)(b * S_LEN + qg0 + 8)) * DM + base;
        Out[ro0 + pos0    ] = f2tf32(oacc[nf][0] * inv0);
        Out[ro0 + pos0 + 2] = f2tf32(oacc[nf][1] * inv0);
        Out[ro1 + pos0    ] = f2tf32(oacc[nf][2] * inv1);
        Out[ro1 + pos0 + 2] = f2tf32(oacc[nf][3] * inv1);
    }
}

// ============================================================
extern "C" void kernel_launch(void* const* d_in, const int* in_sizes, int n_in,
                              void* d_out, int out_size)
{
    const float* hidden = (const float*)d_in[0];
    const float* w_qkv  = (const float*)d_in[1];
    const float* w_out  = (const float*)d_in[2];
    const void*  attn_mask = d_in[3];
    // d_in[4] = causal_mask (implicit)
    const int* pos_xyz = (const int*)d_in[5];
    float* out = (float*)d_out;

    uint32_t *hidp, *wqkvp, *woutp, *ks, *vt, *ao;
    float *q;
    int* lens;
    cudaGetSymbolAddress((void**)&hidp,  g_hid_p);
    cudaGetSymbolAddress((void**)&wqkvp, g_wqkv_p);
    cudaGetSymbolAddress((void**)&woutp, g_wout_p);
    cudaGetSymbolAddress((void**)&q,     g_q);
    cudaGetSymbolAddress((void**)&ks,    g_ks);
    cudaGetSymbolAddress((void**)&vt,    g_vt);
    cudaGetSymbolAddress((void**)&ao,    g_ao);
    cudaGetSymbolAddress((void**)&lens,  g_len);

    compute_lens<<<BB, 256>>>(attn_mask);

    // 0. Pre-convert GEMM operands to paired tf32
    {
        int n1 = M_TOK * DM;
        cvt_pair<<<(n1 + 255) / 256, 256>>>(hidden, hidp, n1);
        int n2 = 3 * DM * DM;
        cvt_pair<<<(n2 + 255) / 256, 256>>>(w_qkv, wqkvp, n2);
        int n3 = DM * DM;
        cvt_pair<<<(n3 + 255) / 256, 256>>>(w_out, woutp, n3);
    }

    // 1. QKV projection + fused RoPE/scatter (paired operands)
    {
        dim3 grid(3 * DM / 128, M_TOK / 128);
        gemm_qkv_rope<<<grid, 256>>>(hidp, wqkvp, pos_xyz, q, ks, vt);
    }

    // 2. Flash attention (writes paired-tf32 attention output)
    {
        cudaFuncSetAttribute(flash_attn_tf32,
                             cudaFuncAttributeMaxDynamicSharedMemorySize,
                             FA_SMEM_BYTES);
        dim3 grid(S_LEN / 64, BB * NH);
        flash_attn_tf32<<<grid, 128, FA_SMEM_BYTES>>>(q, ks, vt, lens, ao);
    }

    // 3. Output projection (paired operands)
    {
        dim3 grid(DM / 128, M_TOK / 128);
        gemm_out<<<grid, 256>>>(ao, woutp, out, M_TOK, DM, DM);
    }
}

// round 9
// speedup vs baseline: 3.1757x; 1.0093x over previous
#include <cuda_runtime.h>
#include <math.h>
#include <stdint.h>

#define S_LEN 2048
#define NH 16
#define HD 64
#define DM 1024
#define BB 2
#define M_TOK (BB * S_LEN)   // 4096

// -------- scratch (static device globals; allocation-free) --------
__device__ uint32_t g_hid_p[(size_t)M_TOK * DM];     // hidden, tf32 paired
__device__ uint32_t g_wqkv_p[(size_t)3 * DM * DM];   // w_qkv, tf32 paired
__device__ uint32_t g_wout_p[(size_t)DM * DM];       // w_out, tf32 paired
__device__ float    g_q [(size_t)M_TOK * DM];        // [B,H,S,Dh] f32
__device__ uint32_t g_ks[(size_t)M_TOK * DM];        // K tf32 (hi)
__device__ uint32_t g_vt[(size_t)M_TOK * DM];        // V tf32
__device__ uint32_t g_ao[(size_t)M_TOK * DM];        // attn out, tf32 paired
__device__ int      g_len[BB];

__device__ __forceinline__ uint32_t f2tf32(float f) {
    uint32_t r;
    asm("cvt.rna.tf32.f32 %0, %1;" : "=r"(r) : "f"(f));
    return r;
}

#define MMA_TF32(c, a, b0, b1)                                              \
    asm volatile(                                                           \
        "mma.sync.aligned.m16n8k8.row.col.f32.tf32.tf32.f32 "               \
        "{%0,%1,%2,%3}, {%4,%5,%6,%7}, {%8,%9}, {%0,%1,%2,%3};"             \
        : "+f"((c)[0]), "+f"((c)[1]), "+f"((c)[2]), "+f"((c)[3])            \
        : "r"((a)[0]), "r"((a)[1]), "r"((a)[2]), "r"((a)[3]),               \
          "r"(b0), "r"(b1))

__device__ __forceinline__ void cpa16(void* smem, const void* gmem) {
    uint32_t s = (uint32_t)__cvta_generic_to_shared(smem);
    asm volatile("cp.async.cg.shared.global [%0], [%1], 16;" :: "r"(s), "l"(gmem));
}
#define CPA_COMMIT() asm volatile("cp.async.commit_group;")
#define CPA_WAIT1()  asm volatile("cp.async.wait_group 1;")
#define CPA_WAIT2()  asm volatile("cp.async.wait_group 2;")

// ============================================================
// Mask length extraction — dtype-agnostic (prefix-true mask).
// ============================================================
__global__ void compute_lens(const void* __restrict__ mask)
{
    __shared__ int cnt;
    const int b = blockIdx.x;
    if (threadIdx.x == 0) cnt = 0;
    __syncthreads();

    const unsigned char* bytes = (const unsigned char*)mask;
    int dtype;
    if (*(const float*)mask == 1.0f) dtype = 2;
    else if (bytes[0] == 1 && bytes[1] == 0) dtype = 1;
    else dtype = 0;

    int local = 0;
    for (int s = threadIdx.x; s < S_LEN; s += blockDim.x) {
        int v;
        if (dtype == 2)      v = (((const float*)mask)[b * S_LEN + s] != 0.0f);
        else if (dtype == 1) v = (((const int*)mask)[b * S_LEN + s] != 0);
        else                 v = (bytes[b * S_LEN + s] != 0);
        local += v;
    }
    atomicAdd(&cnt, local);
    __syncthreads();
    if (threadIdx.x == 0) g_len[b] = cnt;
}

// ============================================================
// Convert f32 -> tf32 with K-pair interleave.
// ============================================================
__global__ void cvt_pair(const float* __restrict__ in,
                         uint32_t* __restrict__ out, int n)
{
    int idx = blockIdx.x * blockDim.x + threadIdx.x;
    if (idx >= n) return;
    int blk = idx >> 3, p = idx & 7;
    int c = (p & 1) ? ((p >> 1) + 4) : (p >> 1);
    out[idx] = f2tf32(in[(size_t)blk * 8 + c]);
}

// ============================================================
// Paired-tf32 GEMM body (cp.async double-buffered).
// ============================================================
#define GSP 20   // uint2 per smem row

struct GemmCtx {
    float c[4][4][4];
    int bm, bn, wm, wn, lr, lc;
};

template <typename EPI>
__device__ __forceinline__ void gemm_tf32p_body(
    const uint32_t* __restrict__ A, const uint32_t* __restrict__ B,
    int M, int N, int K, uint2* As, uint2* Bs, EPI epi)
{
    const int bm = blockIdx.y * 128;
    const int bn = blockIdx.x * 128;
    const int tid = threadIdx.x;
    const int wid = tid >> 5;
    const int lane = tid & 31;
    const int wm = (wid & 1) * 64;
    const int wn = (wid >> 1) * 32;
    const int lr = lane >> 2;
    const int lc = lane & 3;

    GemmCtx g;
    g.bm = bm; g.bn = bn; g.wm = wm; g.wn = wn; g.lr = lr; g.lc = lc;
#pragma unroll
    for (int i = 0; i < 4; i++)
#pragma unroll
        for (int j = 0; j < 4; j++)
#pragma unroll
            for (int r = 0; r < 4; r++) g.c[i][j][r] = 0.f;

    auto issue = [&](int st, int k0 /*u32 units*/) {
#pragma unroll
        for (int i = 0; i < 4; i++) {
            int cid = tid + i * 256;
            int row = cid >> 3;
            int cc  = (cid & 7) * 2;
            cpa16(&As[st * 128 * GSP + row * GSP + cc],
                  &A[(size_t)(bm + row) * K + k0 + cc * 2]);
            cpa16(&Bs[st * 128 * GSP + row * GSP + cc],
                  &B[(size_t)(bn + row) * K + k0 + cc * 2]);
        }
        CPA_COMMIT();
    };

    const int nIt = K / 32;
    issue(0, 0);

    for (int it = 0; it < nIt; it++) {
        const int st = it & 1;
        if (it + 1 < nIt) issue(st ^ 1, (it + 1) * 32);
        else CPA_COMMIT();
        CPA_WAIT1();
        __syncthreads();

        const uint2* Asb = As + st * 128 * GSP;
        const uint2* Bsb = Bs + st * 128 * GSP;
#pragma unroll
        for (int ks = 0; ks < 4; ks++) {
            uint32_t af[4][4], bf[4][2];
#pragma unroll
            for (int mf = 0; mf < 4; mf++) {
                int r0 = wm + mf * 16 + lr;
                uint2 x = Asb[(r0    ) * GSP + ks * 4 + lc];
                uint2 y = Asb[(r0 + 8) * GSP + ks * 4 + lc];
                af[mf][0] = x.x; af[mf][1] = y.x;
                af[mf][2] = x.y; af[mf][3] = y.y;
            }
#pragma unroll
            for (int nf = 0; nf < 4; nf++) {
                uint2 z = Bsb[(wn + nf * 8 + lr) * GSP + ks * 4 + lc];
                bf[nf][0] = z.x; bf[nf][1] = z.y;
            }
#pragma unroll
            for (int mf = 0; mf < 4; mf++)
#pragma unroll
                for (int nf = 0; nf < 4; nf++)
                    MMA_TF32(g.c[mf][nf], af[mf], bf[nf][0], bf[nf][1]);
        }
        __syncthreads();
    }
    epi(g);
}

// ---- out-projection (2 CTAs/SM) ----
__global__ __launch_bounds__(256, 2) void gemm_out(
    const uint32_t* __restrict__ A, const uint32_t* __restrict__ B,
    float* __restrict__ C, int M, int N, int K)
{
    __shared__ uint2 As[2 * 128 * GSP];
    __shared__ uint2 Bs[2 * 128 * GSP];
    gemm_tf32p_body(A, B, M, N, K, As, Bs, [&](GemmCtx& g) {
#pragma unroll
        for (int mf = 0; mf < 4; mf++)
#pragma unroll
            for (int nf = 0; nf < 4; nf++) {
                int row = g.bm + g.wm + mf * 16 + g.lr;
                int col = g.bn + g.wn + nf * 8 + g.lc * 2;
                *(float2*)&C[(size_t)row * N + col] =
                    make_float2(g.c[mf][nf][0], g.c[mf][nf][1]);
                *(float2*)&C[(size_t)(row + 8) * N + col] =
                    make_float2(g.c[mf][nf][2], g.c[mf][nf][3]);
            }
    });
}

// ---- QKV GEMM with fused RoPE epilogue (2 CTAs/SM) ----
__global__ __launch_bounds__(256, 2) void gemm_qkv_rope(
    const uint32_t* __restrict__ A, const uint32_t* __restrict__ B,
    const int* __restrict__ pos_xyz,
    float* __restrict__ Q, uint32_t* __restrict__ Ks,
    uint32_t* __restrict__ Vt)
{
    __shared__ uint2 As[2 * 128 * GSP];
    __shared__ uint2 Bs[2 * 128 * GSP];
    gemm_tf32p_body(A, B, M_TOK, 3 * DM, DM, As, Bs, [&](GemmCtx& g) {
        int   pP[4], hP[4], dP[4], axP[4];
        float invP[4];
#pragma unroll
        for (int nf = 0; nf < 4; nf++) {
            int col = g.bn + g.wn + nf * 8 + g.lc * 2;
            pP[nf] = col >> 10;
            int rem = col & 1023;
            hP[nf] = rem >> 6;
            int d = rem & 63;
            dP[nf] = d;
            int axis, dim, dd;
            if (d < 20)      { axis = 0; dim = 20; dd = d; }
            else if (d < 40) { axis = 1; dim = 20; dd = d - 20; }
            else             { axis = 2; dim = 24; dd = d - 40; }
            axP[nf] = axis;
            invP[nf] = exp2f(-13.287712379549449f * (float)dd / (float)dim);
        }
#pragma unroll
        for (int mf = 0; mf < 4; mf++) {
#pragma unroll
            for (int rr = 0; rr < 2; rr++) {
                int m = g.bm + g.wm + mf * 16 + g.lr + rr * 8;
                int b = m >> 11, s = m & (S_LEN - 1);
#pragma unroll
                for (int nf = 0; nf < 4; nf++) {
                    float c0 = g.c[mf][nf][rr * 2];
                    float c1 = g.c[mf][nf][rr * 2 + 1];
                    size_t o = ((size_t)(b * NH + hP[nf]) * S_LEN + s) * HD + dP[nf];
                    if (pP[nf] == 2) {
                        Vt[o] = f2tf32(c0); Vt[o + 1] = f2tf32(c1);
                    } else {
                        float pos = (float)pos_xyz[m * 3 + axP[nf]];
                        float sn, cs;
                        sincosf(pos * invP[nf], &sn, &cs);
                        float o0 = c0 * cs - c1 * sn;
                        float o1 = c1 * cs + c0 * sn;
                        if (pP[nf] == 0) { Q[o] = o0; Q[o + 1] = o1; }
                        else { Ks[o] = f2tf32(o0); Ks[o + 1] = f2tf32(o1); }
                    }
                }
            }
        }
    });
}

// ============================================================
// Flash attention (unchanged from R8).
// ============================================================
#define FS_K 68
#define FS_V 72
#define FS_PS 76
#define FA_K_WORDS (2 * 64 * FS_K)
#define FA_V_WORDS (64 * FS_V)
#define FA_PS_WORDS (4 * 16 * FS_PS)
#define FA_SMEM_BYTES ((FA_K_WORDS + FA_V_WORDS + FA_PS_WORDS) * 4)

__global__ __launch_bounds__(128, 3) void flash_attn_tf32(
    const float* __restrict__ Q, const uint32_t* __restrict__ K,
    const uint32_t* __restrict__ V, const int* __restrict__ lens,
    uint32_t* __restrict__ Out)
{
    extern __shared__ uint32_t smu[];
    uint32_t* Ksm = smu;
    uint32_t* Vsm = smu + FA_K_WORDS;
    uint32_t* Ps  = smu + FA_K_WORDS + FA_V_WORDS;

    const int qt = (int)(gridDim.x - 1 - blockIdx.x);
    const int bh = blockIdx.y;
    const int b  = bh >> 4;
    const int h  = bh & 15;
    const float*    Qg = Q + ((size_t)bh * S_LEN + qt * 64) * HD;
    const uint32_t* Kg = K + (size_t)bh * S_LEN * HD;
    const uint32_t* Vg = V + (size_t)bh * S_LEN * HD;
    const int klen = lens[b];

    const int tid = threadIdx.x;
    const int wq = tid >> 5;
    const int lane = tid & 31;
    const int lr = lane >> 2;
    const int lc = lane & 3;
    const int r0 = wq * 16 + lr;

    const int nt = min(qt + 1, (klen + 63) >> 6);

    auto issue_K = [&](int st, int t) {
#pragma unroll
        for (int i = 0; i < 8; i++) {
            int cid = tid + i * 128;
            int row = cid >> 4;
            int col = (cid & 15) * 4;
            cpa16(&Ksm[st * 64 * FS_K + row * FS_K + col],
                  &Kg[(size_t)(t * 64 + row) * HD + col]);
        }
    };
    auto issue_V = [&](int t) {
#pragma unroll
        for (int i = 0; i < 8; i++) {
            int cid = tid + i * 128;
            int row = cid >> 4;
            int col = (cid & 15) * 4;
            cpa16(&Vsm[row * FS_V + col],
                  &Vg[(size_t)(t * 64 + row) * HD + col]);
        }
    };

    issue_K(0, 0);
    CPA_COMMIT();

    float* Qstage = (float*)Ps;
    for (int idx = tid; idx < 64 * 16; idx += 128) {
        int q = idx >> 4, d0 = (idx & 15) << 2;
        float4 v = *(const float4*)&Qg[q * HD + d0];
        Qstage[q * FS_K + d0 + 0] = v.x;
        Qstage[q * FS_K + d0 + 1] = v.y;
        Qstage[q * FS_K + d0 + 2] = v.z;
        Qstage[q * FS_K + d0 + 3] = v.w;
    }
    __syncthreads();

    uint32_t qh[8][4], ql[8][4];
#pragma unroll
    for (int kb = 0; kb < 8; kb++) {
        float f[4];
        f[0] = Qstage[(r0    ) * FS_K + kb * 8 + lc    ];
        f[1] = Qstage[(r0 + 8) * FS_K + kb * 8 + lc    ];
        f[2] = Qstage[(r0    ) * FS_K + kb * 8 + lc + 4];
        f[3] = Qstage[(r0 + 8) * FS_K + kb * 8 + lc + 4];
#pragma unroll
        for (int i = 0; i < 4; i++) {
            qh[kb][i] = f2tf32(f[i]);
            ql[kb][i] = f2tf32(f[i] - __uint_as_float(qh[kb][i]));
        }
    }
    __syncthreads();

    float oacc[8][4];
#pragma unroll
    for (int nf = 0; nf < 8; nf++)
#pragma unroll
        for (int i = 0; i < 4; i++) oacc[nf][i] = 0.f;
    float mrow0 = -1e30f, mrow1 = -1e30f;
    float lrow0 = 0.f, lrow1 = 0.f;

    const int qg0 = qt * 64 + r0;

    for (int t = 0; t < nt; t++) {
        const int st = t & 1;
        issue_V(t);
        CPA_COMMIT();
        if (t + 1 < nt) issue_K(st ^ 1, t + 1);
        CPA_COMMIT();
        CPA_WAIT2();
        __syncthreads();

        const uint32_t* Kt = Ksm + st * 64 * FS_K;

        float sf[8][4];
#pragma unroll
        for (int nf = 0; nf < 8; nf++)
#pragma unroll
            for (int i = 0; i < 4; i++) sf[nf][i] = 0.f;

#pragma unroll
        for (int kb = 0; kb < 8; kb++) {
#pragma unroll
            for (int nf = 0; nf < 8; nf++) {
                int n0 = nf * 8 + lr;
                uint32_t k0 = Kt[n0 * FS_K + kb * 8 + lc    ];
                uint32_t k1 = Kt[n0 * FS_K + kb * 8 + lc + 4];
                MMA_TF32(sf[nf], qh[kb], k0, k1);
                MMA_TF32(sf[nf], ql[kb], k0, k1);
            }
        }

        const bool edge = (t == qt) || ((t + 1) * 64 > klen);
#pragma unroll
        for (int nf = 0; nf < 8; nf++) {
            if (edge) {
                int kg = t * 64 + nf * 8 + lc * 2;
                sf[nf][0] = (kg     <= qg0     && kg     < klen) ? sf[nf][0] * 0.125f : -1e30f;
                sf[nf][1] = (kg + 1 <= qg0     && kg + 1 < klen) ? sf[nf][1] * 0.125f : -1e30f;
                sf[nf][2] = (kg     <= qg0 + 8 && kg     < klen) ? sf[nf][2] * 0.125f : -1e30f;
                sf[nf][3] = (kg + 1 <= qg0 + 8 && kg + 1 < klen) ? sf[nf][3] * 0.125f : -1e30f;
            } else {
                sf[nf][0] *= 0.125f; sf[nf][1] *= 0.125f;
                sf[nf][2] *= 0.125f; sf[nf][3] *= 0.125f;
            }
        }

        float m0 = -1e30f, m1 = -1e30f;
#pragma unroll
        for (int nf = 0; nf < 8; nf++) {
            m0 = fmaxf(m0, fmaxf(sf[nf][0], sf[nf][1]));
            m1 = fmaxf(m1, fmaxf(sf[nf][2], sf[nf][3]));
        }
        m0 = fmaxf(m0, __shfl_xor_sync(0xffffffffu, m0, 1));
        m0 = fmaxf(m0, __shfl_xor_sync(0xffffffffu, m0, 2));
        m1 = fmaxf(m1, __shfl_xor_sync(0xffffffffu, m1, 1));
        m1 = fmaxf(m1, __shfl_xor_sync(0xffffffffu, m1, 2));

        float mn0 = fmaxf(mrow0, m0), mn1 = fmaxf(mrow1, m1);
        float al0 = __expf(mrow0 - mn0), al1 = __expf(mrow1 - mn1);
        mrow0 = mn0; mrow1 = mn1;

        float s0 = 0.f, s1 = 0.f;
#pragma unroll
        for (int nf = 0; nf < 8; nf++) {
            float p0 = __expf(sf[nf][0] - mn0);
            float p1 = __expf(sf[nf][1] - mn0);
            float p2 = __expf(sf[nf][2] - mn1);
            float p3 = __expf(sf[nf][3] - mn1);
            sf[nf][0] = p0; sf[nf][1] = p1; sf[nf][2] = p2; sf[nf][3] = p3;
            s0 += p0 + p1; s1 += p2 + p3;
        }
        s0 += __shfl_xor_sync(0xffffffffu, s0, 1);
        s0 += __shfl_xor_sync(0xffffffffu, s0, 2);
        s1 += __shfl_xor_sync(0xffffffffu, s1, 1);
        s1 += __shfl_xor_sync(0xffffffffu, s1, 2);
        lrow0 = lrow0 * al0 + s0;
        lrow1 = lrow1 * al1 + s1;

#pragma unroll
        for (int nf = 0; nf < 8; nf++) {
            oacc[nf][0] *= al0; oacc[nf][1] *= al0;
            oacc[nf][2] *= al1; oacc[nf][3] *= al1;
        }

        uint32_t* PsW = Ps + wq * 16 * FS_PS;
#pragma unroll
        for (int nf = 0; nf < 8; nf++) {
            int col = nf * 8 + lc * 2;
            PsW[ lr      * FS_PS + col    ] = f2tf32(sf[nf][0]);
            PsW[ lr      * FS_PS + col + 1] = f2tf32(sf[nf][1]);
            PsW[(lr + 8) * FS_PS + col    ] = f2tf32(sf[nf][2]);
            PsW[(lr + 8) * FS_PS + col + 1] = f2tf32(sf[nf][3]);
        }
        __syncwarp();

        CPA_WAIT1();
        __syncthreads();

#pragma unroll
        for (int kb = 0; kb < 8; kb++) {
            uint32_t af[4];
            af[0] = PsW[ lr      * FS_PS + kb * 8 + lc    ];
            af[1] = PsW[(lr + 8) * FS_PS + kb * 8 + lc    ];
            af[2] = PsW[ lr      * FS_PS + kb * 8 + lc + 4];
            af[3] = PsW[(lr + 8) * FS_PS + kb * 8 + lc + 4];
#pragma unroll
            for (int nf = 0; nf < 8; nf++) {
                int n0 = nf * 8 + lr;
                uint32_t b0 = Vsm[(kb * 8 + lc    ) * FS_V + n0];
                uint32_t b1 = Vsm[(kb * 8 + lc + 4) * FS_V + n0];
                MMA_TF32(oacc[nf], af, b0, b1);
            }
        }
        __syncthreads();
    }

    const int pos0 = ((lc & 1) << 2) + (lc >> 1);
    float inv0 = 1.0f / lrow0, inv1 = 1.0f / lrow1;
#pragma unroll
    for (int nf = 0; nf < 8; nf++) {
        int base = h * HD + nf * 8;
        size_t ro0 = ((size_t)(b * S_LEN + qg0    )) * DM + base;
        size_t ro1 = ((size_t)(b * S_LEN + qg0 + 8)) * DM + base;
        Out[ro0 + pos0    ] = f2tf32(oacc[nf][0] * inv0);
        Out[ro0 + pos0 + 2] = f2tf32(oacc[nf][1] * inv0);
        Out[ro1 + pos0    ] = f2tf32(oacc[nf][2] * inv1);
        Out[ro1 + pos0 + 2] = f2tf32(oacc[nf][3] * inv1);
    }
}

// ============================================================
extern "C" void kernel_launch(void* const* d_in, const int* in_sizes, int n_in,
                              void* d_out, int out_size)
{
    const float* hidden = (const float*)d_in[0];
    const float* w_qkv  = (const float*)d_in[1];
    const float* w_out  = (const float*)d_in[2];
    const void*  attn_mask = d_in[3];
    // d_in[4] = causal_mask (implicit)
    const int* pos_xyz = (const int*)d_in[5];
    float* out = (float*)d_out;

    uint32_t *hidp, *wqkvp, *woutp, *ks, *vt, *ao;
    float *q;
    int* lens;
    cudaGetSymbolAddress((void**)&hidp,  g_hid_p);
    cudaGetSymbolAddress((void**)&wqkvp, g_wqkv_p);
    cudaGetSymbolAddress((void**)&woutp, g_wout_p);
    cudaGetSymbolAddress((void**)&q,     g_q);
    cudaGetSymbolAddress((void**)&ks,    g_ks);
    cudaGetSymbolAddress((void**)&vt,    g_vt);
    cudaGetSymbolAddress((void**)&ao,    g_ao);
    cudaGetSymbolAddress((void**)&lens,  g_len);

    compute_lens<<<BB, 256>>>(attn_mask);

    // 0. Pre-convert GEMM operands to paired tf32
    {
        int n1 = M_TOK * DM;
        cvt_pair<<<(n1 + 255) / 256, 256>>>(hidden, hidp, n1);
        int n2 = 3 * DM * DM;
        cvt_pair<<<(n2 + 255) / 256, 256>>>(w_qkv, wqkvp, n2);
        int n3 = DM * DM;
        cvt_pair<<<(n3 + 255) / 256, 256>>>(w_out, woutp, n3);
    }

    // 1. QKV projection + fused RoPE/scatter
    {
        dim3 grid(3 * DM / 128, M_TOK / 128);
        gemm_qkv_rope<<<grid, 256>>>(hidp, wqkvp, pos_xyz, q, ks, vt);
    }

    // 2. Flash attention
    {
        cudaFuncSetAttribute(flash_attn_tf32,
                             cudaFuncAttributeMaxDynamicSharedMemorySize,
                             FA_SMEM_BYTES);
        dim3 grid(S_LEN / 64, BB * NH);
        flash_attn_tf32<<<grid, 128, FA_SMEM_BYTES>>>(q, ks, vt, lens, ao);
    }

    // 3. Output projection
    {
        dim3 grid(DM / 128, M_TOK / 128);
        gemm_out<<<grid, 256>>>(ao, woutp, out, M_TOK, DM, DM);
    }
}